// round 1
// baseline (speedup 1.0000x reference)
#include <cuda_runtime.h>
#include <math.h>

// Problem constants
#define BTN 32      // B*T
#define LLEN 512    // L
#define DDIM 512    // D
#define NH 8        // H
#define ED 64       // KD == VD

// Scratch (device globals: allocation-free rule)
__device__ float g_Q[BTN * LLEN * DDIM];           // [bt][l][h*64+e]
__device__ float g_K[BTN * LLEN * DDIM];
__device__ float g_V[BTN * LLEN * DDIM];
__device__ float g_A[BTN * NH * LLEN * ED];        // [bt*8+h][l][e] (pre-head-weight attn out)

// ---------------------------------------------------------------------------
// Projection GEMM: C[M=16384, N=512] = X[M, K=512] @ W[K, N]
// 128x128 block tile, BK=16, 256 threads, 8x8 microtile (split 4+4 quadrants)
// blockIdx.z selects {Q, K, V} projection.
// ---------------------------------------------------------------------------
__global__ void __launch_bounds__(256) proj_kernel(
    const float* __restrict__ Xq, const float* __restrict__ Xk, const float* __restrict__ Xv,
    const float* __restrict__ Wq, const float* __restrict__ Wk, const float* __restrict__ Wv)
{
    const float* A; const float* B; float* C;
    if (blockIdx.z == 0)      { A = Xq; B = Wq; C = g_Q; }
    else if (blockIdx.z == 1) { A = Xk; B = Wk; C = g_K; }
    else                      { A = Xv; B = Wv; C = g_V; }

    __shared__ float As[16][128];   // transposed: As[k][m]
    __shared__ float Bs[16][128];   // Bs[k][n]

    const int tid = threadIdx.x;
    const int tx  = tid & 15;
    const int ty  = tid >> 4;
    const int m0  = blockIdx.y * 128;
    const int n0  = blockIdx.x * 128;

    float acc[8][8];
#pragma unroll
    for (int i = 0; i < 8; i++)
#pragma unroll
        for (int j = 0; j < 8; j++) acc[i][j] = 0.f;

    for (int k0 = 0; k0 < 512; k0 += 16) {
        // Load A tile (128x16) transposed into As
#pragma unroll
        for (int it = 0; it < 2; it++) {
            int idx = tid + it * 256;           // 0..511 float4s
            int r = idx >> 2, c4 = idx & 3;
            float4 v = *(const float4*)&A[(size_t)(m0 + r) * 512 + k0 + c4 * 4];
            As[c4 * 4 + 0][r] = v.x;
            As[c4 * 4 + 1][r] = v.y;
            As[c4 * 4 + 2][r] = v.z;
            As[c4 * 4 + 3][r] = v.w;
        }
        // Load B tile (16x128)
#pragma unroll
        for (int it = 0; it < 2; it++) {
            int idx = tid + it * 256;
            int r = idx >> 5, c4 = idx & 31;
            *(float4*)&Bs[r][c4 * 4] =
                *(const float4*)&B[(size_t)(k0 + r) * 512 + n0 + c4 * 4];
        }
        __syncthreads();

#pragma unroll
        for (int k = 0; k < 16; k++) {
            float4 a0 = *(float4*)&As[k][ty * 4];
            float4 a1 = *(float4*)&As[k][64 + ty * 4];
            float4 b0 = *(float4*)&Bs[k][tx * 4];
            float4 b1 = *(float4*)&Bs[k][64 + tx * 4];
            float av[8] = {a0.x, a0.y, a0.z, a0.w, a1.x, a1.y, a1.z, a1.w};
            float bv[8] = {b0.x, b0.y, b0.z, b0.w, b1.x, b1.y, b1.z, b1.w};
#pragma unroll
            for (int i = 0; i < 8; i++)
#pragma unroll
                for (int j = 0; j < 8; j++) acc[i][j] += av[i] * bv[j];
        }
        __syncthreads();
    }

#pragma unroll
    for (int i = 0; i < 8; i++) {
        int r = m0 + ((i < 4) ? (ty * 4 + i) : (64 + ty * 4 + i - 4));
        float4 v0 = make_float4(acc[i][0], acc[i][1], acc[i][2], acc[i][3]);
        float4 v1 = make_float4(acc[i][4], acc[i][5], acc[i][6], acc[i][7]);
        *(float4*)&C[(size_t)r * 512 + n0 + tx * 4]      = v0;
        *(float4*)&C[(size_t)r * 512 + n0 + 64 + tx * 4] = v1;
    }
}

// ---------------------------------------------------------------------------
// Attention: one CTA per (b,t,h, 64-row l-chunk). Full 64x512 score strip in
// smem, plain softmax (matches reference's multiplicative-mask semantics
// exactly), then P@V with streamed V tiles.
// Shared memory layout (floats):
//   sQT  [64 e][68]   e-major Q chunk (transposed)        4352 floats
//   sKV  union: sKT [64 e][132]  or  sV [128 s][68]       8704 floats
//   sS   [64 l][516]  scores / probabilities             33024 floats
// total 46080 floats = 184320 bytes (1 CTA/SM)
// ---------------------------------------------------------------------------
#define SM_Q   0
#define SM_KV  4352
#define SM_S   13056
#define ATTN_SMEM_BYTES (46080 * 4)

__global__ void __launch_bounds__(256) attn_kernel(
    const float* __restrict__ mask,
    const float* __restrict__ tau,
    const float* __restrict__ delta,
    const float* __restrict__ w_head)
{
    extern __shared__ float sm[];
    float* sQT = sm + SM_Q;
    float* sKV = sm + SM_KV;
    float* sS  = sm + SM_S;

    const int tid  = threadIdx.x;
    const int tx   = tid & 15;
    const int ty   = tid >> 4;
    const int bth  = blockIdx.x;          // 0..255
    const int bt   = bth >> 3;
    const int h    = bth & 7;
    const int l0   = blockIdx.y * 64;

    const float tauv   = tau[0];
    const float deltav = delta[0];
    const float scale  = rsqrtf(64.0f);   // 1/sqrt(KD) = 0.125 exactly

    const float* Qbase = g_Q + ((size_t)bt * 512 + l0) * 512 + h * 64;
    const float* Kbase = g_K + (size_t)bt * 512 * 512 + h * 64;
    const float* Vbase = g_V + (size_t)bt * 512 * 512 + h * 64;

    // ---- load Q chunk transposed: sQT[e][l] ----
#pragma unroll
    for (int it = 0; it < 4; it++) {
        int idx = tid + it * 256;           // 0..1023 float4s
        int r = idx >> 4, e4 = idx & 15;
        float4 v = *(const float4*)&Qbase[(size_t)r * 512 + e4 * 4];
        sQT[(e4 * 4 + 0) * 68 + r] = v.x;
        sQT[(e4 * 4 + 1) * 68 + r] = v.y;
        sQT[(e4 * 4 + 2) * 68 + r] = v.z;
        sQT[(e4 * 4 + 3) * 68 + r] = v.w;
    }

    // ---- QK^T, scaled + masked, into sS ----
    for (int sc = 0; sc < 4; sc++) {
        __syncthreads();   // protects sKV reuse across iterations (and sQT 1st iter)
        // load K tile (128 x 64) transposed: sKT[e][s]
#pragma unroll
        for (int it = 0; it < 8; it++) {
            int idx = tid + it * 256;        // 0..2047 float4s
            int r = idx >> 4, e4 = idx & 15;
            float4 v = *(const float4*)&Kbase[(size_t)(sc * 128 + r) * 512 + e4 * 4];
            sKV[(e4 * 4 + 0) * 132 + r] = v.x;
            sKV[(e4 * 4 + 1) * 132 + r] = v.y;
            sKV[(e4 * 4 + 2) * 132 + r] = v.z;
            sKV[(e4 * 4 + 3) * 132 + r] = v.w;
        }
        __syncthreads();

        float acc[4][8];
#pragma unroll
        for (int i = 0; i < 4; i++)
#pragma unroll
            for (int j = 0; j < 8; j++) acc[i][j] = 0.f;

#pragma unroll 4
        for (int e = 0; e < 64; e++) {
            float4 q  = *(float4*)&sQT[e * 68 + ty * 4];
            float4 kA = *(float4*)&sKV[e * 132 + tx * 4];
            float4 kB = *(float4*)&sKV[e * 132 + 64 + tx * 4];
            float qv[4] = {q.x, q.y, q.z, q.w};
            float kv[8] = {kA.x, kA.y, kA.z, kA.w, kB.x, kB.y, kB.z, kB.w};
#pragma unroll
            for (int i = 0; i < 4; i++)
#pragma unroll
                for (int j = 0; j < 8; j++) acc[i][j] += qv[i] * kv[j];
        }

        // scale + mask, write to sS
#pragma unroll
        for (int i = 0; i < 4; i++) {
            int li = ty * 4 + i;
            int gl = l0 + li;
            const float* mrow = mask + (size_t)gl * 512 + sc * 128;
            float4 mA = *(const float4*)&mrow[tx * 4];
            float4 mB = *(const float4*)&mrow[64 + tx * 4];
            float4 rA, rB;
            rA.x = (acc[i][0] * tauv + deltav) * scale * mA.x;
            rA.y = (acc[i][1] * tauv + deltav) * scale * mA.y;
            rA.z = (acc[i][2] * tauv + deltav) * scale * mA.z;
            rA.w = (acc[i][3] * tauv + deltav) * scale * mA.w;
            rB.x = (acc[i][4] * tauv + deltav) * scale * mB.x;
            rB.y = (acc[i][5] * tauv + deltav) * scale * mB.y;
            rB.z = (acc[i][6] * tauv + deltav) * scale * mB.z;
            rB.w = (acc[i][7] * tauv + deltav) * scale * mB.w;
            *(float4*)&sS[li * 516 + sc * 128 + tx * 4]      = rA;
            *(float4*)&sS[li * 516 + sc * 128 + 64 + tx * 4] = rB;
        }
    }
    __syncthreads();

    // ---- softmax over s (one warp per row group) ----
    {
        const int lane = tid & 31;
        const int w    = tid >> 5;
        for (int r = 0; r < 8; r++) {
            int li = w * 8 + r;
            float* row = sS + li * 516;
            float4* row4 = (float4*)row;
            float m = -1e30f;
#pragma unroll
            for (int jj = lane; jj < 128; jj += 32) {
                float4 v = row4[jj];
                m = fmaxf(m, fmaxf(fmaxf(v.x, v.y), fmaxf(v.z, v.w)));
            }
#pragma unroll
            for (int o = 16; o; o >>= 1) m = fmaxf(m, __shfl_xor_sync(0xffffffffu, m, o));
            float sum = 0.f;
#pragma unroll
            for (int jj = lane; jj < 128; jj += 32) {
                float4 v = row4[jj];
                v.x = __expf(v.x - m);
                v.y = __expf(v.y - m);
                v.z = __expf(v.z - m);
                v.w = __expf(v.w - m);
                row4[jj] = v;
                sum += v.x + v.y + v.z + v.w;
            }
#pragma unroll
            for (int o = 16; o; o >>= 1) sum += __shfl_xor_sync(0xffffffffu, sum, o);
            float inv = 1.0f / sum;
#pragma unroll
            for (int jj = lane; jj < 128; jj += 32) {
                float4 v = row4[jj];
                v.x *= inv; v.y *= inv; v.z *= inv; v.w *= inv;
                row4[jj] = v;
            }
        }
    }
    __syncthreads();

    // ---- P @ V ----
    float o[4][4];
#pragma unroll
    for (int i = 0; i < 4; i++)
#pragma unroll
        for (int j = 0; j < 4; j++) o[i][j] = 0.f;

    for (int sc = 0; sc < 4; sc++) {
        // load V tile (128 x 64) row-major: sV[s][e], stride 68
#pragma unroll
        for (int it = 0; it < 8; it++) {
            int idx = tid + it * 256;
            int r = idx >> 4, e4 = idx & 15;
            *(float4*)&sKV[r * 68 + e4 * 4] =
                *(const float4*)&Vbase[(size_t)(sc * 128 + r) * 512 + e4 * 4];
        }
        __syncthreads();

#pragma unroll 2
        for (int s4 = 0; s4 < 32; s4++) {
            float4 p[4], vv[4];
#pragma unroll
            for (int i = 0; i < 4; i++)
                p[i] = *(float4*)&sS[(ty * 4 + i) * 516 + sc * 128 + s4 * 4];
#pragma unroll
            for (int u = 0; u < 4; u++)
                vv[u] = *(float4*)&sKV[(s4 * 4 + u) * 68 + tx * 4];
#pragma unroll
            for (int i = 0; i < 4; i++) {
                float pv[4] = {p[i].x, p[i].y, p[i].z, p[i].w};
#pragma unroll
                for (int u = 0; u < 4; u++) {
                    o[i][0] += pv[u] * vv[u].x;
                    o[i][1] += pv[u] * vv[u].y;
                    o[i][2] += pv[u] * vv[u].z;
                    o[i][3] += pv[u] * vv[u].w;
                }
            }
        }
        __syncthreads();
    }

    // ---- write per-head attention output ----
    float* dst = g_A + ((size_t)bth * 512 + l0) * 64;
#pragma unroll
    for (int i = 0; i < 4; i++) {
        float4 v = make_float4(o[i][0], o[i][1], o[i][2], o[i][3]);
        *(float4*)&dst[(ty * 4 + i) * 64 + tx * 4] = v;
    }
    (void)w_head;
}

// ---------------------------------------------------------------------------
// Head reduction: out[bt,l,e] = sum_h w_head[h] * g_A[bt*8+h][l][e]
// ---------------------------------------------------------------------------
__global__ void __launch_bounds__(256) reduce_heads(
    const float* __restrict__ w_head, float* __restrict__ out)
{
    int idx = blockIdx.x * 256 + threadIdx.x;     // 0..1048575
    int bt   = idx >> 15;                         // / (512*64)
    int rest = idx & 32767;
    float s = 0.f;
#pragma unroll
    for (int h = 0; h < 8; h++)
        s += w_head[h] * g_A[(((size_t)bt * 8 + h) << 15) + rest];
    out[idx] = s;
}

// ---------------------------------------------------------------------------
extern "C" void kernel_launch(void* const* d_in, const int* in_sizes, int n_in,
                              void* d_out, int out_size)
{
    const float* queries = (const float*)d_in[0];
    const float* keys    = (const float*)d_in[1];
    const float* values  = (const float*)d_in[2];
    const float* mask    = (const float*)d_in[3];
    const float* Wq      = (const float*)d_in[4];
    const float* Wk      = (const float*)d_in[5];
    const float* Wv      = (const float*)d_in[6];
    const float* w_head  = (const float*)d_in[7];
    const float* tau     = (const float*)d_in[8];
    const float* delta   = (const float*)d_in[9];
    float* out = (float*)d_out;
    (void)in_sizes; (void)n_in; (void)out_size;

    cudaFuncSetAttribute(attn_kernel,
                         cudaFuncAttributeMaxDynamicSharedMemorySize,
                         ATTN_SMEM_BYTES);

    // 1) Projections (one fused batched launch: z = {Q,K,V})
    {
        dim3 grid(4, 128, 3);     // N/128, M/128, projection id
        proj_kernel<<<grid, 256>>>(queries, keys, values, Wq, Wk, Wv);
    }

    // 2) Attention per (b,t,h, l-chunk)
    {
        dim3 grid(256, 8);        // bth, l-chunk of 64
        attn_kernel<<<grid, 256, ATTN_SMEM_BYTES>>>(mask, tau, delta, w_head);
    }

    // 3) Weighted head sum
    reduce_heads<<<4096, 256>>>(w_head, out);
}

// round 3
// speedup vs baseline: 1.1659x; 1.1659x over previous
#include <cuda_runtime.h>
#include <cuda_bf16.h>
#include <stdint.h>
#include <math.h>

// Problem constants
#define BTN 32      // B*T
#define LLEN 512    // L
#define DDIM 512    // D
#define NH 8        // H
#define ED 64       // KD == VD
#define MROWS (BTN * LLEN)   // 16384

// Scratch (allocation-free rule -> device globals)
__device__ float g_Q[BTN * LLEN * DDIM];
__device__ float g_K[BTN * LLEN * DDIM];
__device__ float g_V[BTN * LLEN * DDIM];
__device__ float g_A[BTN * NH * LLEN * ED];

// ---------------------------------------------------------------------------
// mma.sync helpers (bf16 -> f32, m16n8k16) + ldmatrix
// ---------------------------------------------------------------------------
__device__ __forceinline__ uint32_t smem_u32(const void* p) {
    uint32_t a;
    asm("{ .reg .u64 t; cvta.to.shared.u64 t, %1; cvt.u32.u64 %0, t; }"
        : "=r"(a) : "l"(p));
    return a;
}

__device__ __forceinline__ void mma_bf16(float* d, const uint32_t* a, const uint32_t* b) {
    asm volatile(
        "mma.sync.aligned.m16n8k16.row.col.f32.bf16.bf16.f32 "
        "{%0,%1,%2,%3}, {%4,%5,%6,%7}, {%8,%9}, {%0,%1,%2,%3};"
        : "+f"(d[0]), "+f"(d[1]), "+f"(d[2]), "+f"(d[3])
        : "r"(a[0]), "r"(a[1]), "r"(a[2]), "r"(a[3]), "r"(b[0]), "r"(b[1]));
}

__device__ __forceinline__ void ldsm_x4(uint32_t* r, uint32_t addr) {
    asm volatile("ldmatrix.sync.aligned.m8n8.x4.shared.b16 {%0,%1,%2,%3}, [%4];"
                 : "=r"(r[0]), "=r"(r[1]), "=r"(r[2]), "=r"(r[3]) : "r"(addr));
}
__device__ __forceinline__ void ldsm_x4_t(uint32_t* r, uint32_t addr) {
    asm volatile("ldmatrix.sync.aligned.m8n8.x4.trans.shared.b16 {%0,%1,%2,%3}, [%4];"
                 : "=r"(r[0]), "=r"(r[1]), "=r"(r[2]), "=r"(r[3]) : "r"(addr));
}

// hi/lo bf16 split
__device__ __forceinline__ void split_bf16(float x, uint16_t& h, uint16_t& l) {
    __nv_bfloat16 hb = __float2bfloat16(x);
    float hf = __bfloat162float(hb);
    __nv_bfloat16 lb = __float2bfloat16(x - hf);
    h = __bfloat16_as_ushort(hb);
    l = __bfloat16_as_ushort(lb);
}

// pack 8 floats -> 8 hi halves (uint4) + 8 lo halves (uint4)
__device__ __forceinline__ void pack8(const float* xs, uint4& hi, uint4& lo) {
    uint16_t hs[8], ls[8];
#pragma unroll
    for (int j = 0; j < 8; j++) split_bf16(xs[j], hs[j], ls[j]);
    hi.x = (uint32_t)hs[0] | ((uint32_t)hs[1] << 16);
    hi.y = (uint32_t)hs[2] | ((uint32_t)hs[3] << 16);
    hi.z = (uint32_t)hs[4] | ((uint32_t)hs[5] << 16);
    hi.w = (uint32_t)hs[6] | ((uint32_t)hs[7] << 16);
    lo.x = (uint32_t)ls[0] | ((uint32_t)ls[1] << 16);
    lo.y = (uint32_t)ls[2] | ((uint32_t)ls[3] << 16);
    lo.z = (uint32_t)ls[4] | ((uint32_t)ls[5] << 16);
    lo.w = (uint32_t)ls[6] | ((uint32_t)ls[7] << 16);
}

// ---------------------------------------------------------------------------
// Projection GEMM on tensor cores (mma.sync bf16 hi/lo split):
//   C[16384, 512] = X[16384, 512] @ W[512, 512], per projection (blockIdx.z)
// CTA 128x128, BK=32, 256 threads (8 warps, warp tile 32x64), double buffer.
// smem halves-pitches: A 40 (conflict-free ldmatrix), B 136.
// ---------------------------------------------------------------------------
#define A_STR 40
#define B_STR 136
#define OFF_AH 0
#define OFF_AL 10240
#define OFF_BH 20480
#define OFF_BL 29184
#define STAGE_BYTES 37888
#define PROJ_SMEM (2 * STAGE_BYTES)

__global__ void __launch_bounds__(256) proj_mma(
    const float* __restrict__ Xq, const float* __restrict__ Xk, const float* __restrict__ Xv,
    const float* __restrict__ Wq, const float* __restrict__ Wk, const float* __restrict__ Wv)
{
    extern __shared__ char smc[];
    const uint32_t sbase = smem_u32(smc);

    const int tid  = threadIdx.x;
    const int wid  = tid >> 5;
    const int lane = tid & 31;
    const int wm   = wid & 3;       // 4 m-warps (32 rows each)
    const int wn   = wid >> 2;      // 2 n-warps (64 cols each)

    const int p  = blockIdx.z;
    const int m0 = blockIdx.y * 128;
    const int n0 = blockIdx.x * 128;

    const float* X = (p == 0) ? Xq : (p == 1) ? Xk : Xv;
    const float* W = (p == 0) ? Wq : (p == 1) ? Wk : Wv;
    float*       C = (p == 0) ? g_Q : (p == 1) ? g_K : g_V;

    // gmem staging mapping
    const int arow = tid >> 1;            // 0..127
    const int akh  = (tid & 1) * 16;      // 0 or 16
    const int brow = tid >> 3;            // 0..31 (k row)
    const int bns  = (tid & 7) * 16;      // n segment

    const float* aptr = X + (size_t)(m0 + arow) * 512 + akh;
    const float* bptr = W + (size_t)brow * 512 + n0 + bns;

    float acc[2][8][4];
#pragma unroll
    for (int i = 0; i < 2; i++)
#pragma unroll
        for (int j = 0; j < 8; j++)
#pragma unroll
            for (int q = 0; q < 4; q++) acc[i][j][q] = 0.f;

    // ldmatrix source addresses (per-lane, byte offsets into stage)
    const int lrow = (lane & 7) | (lane & 8);     // 0..15 pattern
    const int lblk = lane >> 4;                   // 0/1
    // A: row = wm*32 + mt*16 + lrow ; col = k16 + lblk*8
    const uint32_t a_lane_off =
        (uint32_t)(((wm * 32 + lrow) * A_STR + lblk * 8) * 2);
    // B: row = k16 + lrow ; col = wn*64 + np*16 + lblk*8
    const uint32_t b_lane_off =
        (uint32_t)((lrow * B_STR + wn * 64 + lblk * 8) * 2);

    float av[16], bv[16];

    // prologue: load + convert + store chunk 0
    {
#pragma unroll
        for (int i = 0; i < 4; i++) {
            float4 t = *(const float4*)&aptr[i * 4];
            av[i * 4] = t.x; av[i * 4 + 1] = t.y; av[i * 4 + 2] = t.z; av[i * 4 + 3] = t.w;
            float4 u = *(const float4*)&bptr[i * 4];
            bv[i * 4] = u.x; bv[i * 4 + 1] = u.y; bv[i * 4 + 2] = u.z; bv[i * 4 + 3] = u.w;
        }
        uint4 h0, l0, h1, l1;
        pack8(av, h0, l0); pack8(av + 8, h1, l1);
        char* abase = smc + OFF_AH + (arow * A_STR + akh) * 2;
        *(uint4*)(abase)      = h0;  *(uint4*)(abase + 16) = h1;
        *(uint4*)(abase + OFF_AL) = l0;  *(uint4*)(abase + OFF_AL + 16) = l1;
        pack8(bv, h0, l0); pack8(bv + 8, h1, l1);
        char* bbase = smc + OFF_BH + (brow * B_STR + bns) * 2;
        *(uint4*)(bbase)      = h0;  *(uint4*)(bbase + 16) = h1;
        *(uint4*)(bbase + OFF_BL - OFF_BH) = l0;
        *(uint4*)(bbase + OFF_BL - OFF_BH + 16) = l1;
    }
    __syncthreads();

    for (int c = 0; c < 16; c++) {
        const int s = c & 1;
        const uint32_t stg = sbase + s * STAGE_BYTES;

        // issue gmem loads for next chunk (latency overlap with compute)
        if (c < 15) {
            const int k0n = (c + 1) * 32;
            const float* ap = aptr + k0n;
            const float* bp = bptr + (size_t)k0n * 512;
#pragma unroll
            for (int i = 0; i < 4; i++) {
                float4 t = *(const float4*)&ap[i * 4];
                av[i * 4] = t.x; av[i * 4 + 1] = t.y; av[i * 4 + 2] = t.z; av[i * 4 + 3] = t.w;
                float4 u = *(const float4*)&bp[i * 4];
                bv[i * 4] = u.x; bv[i * 4 + 1] = u.y; bv[i * 4 + 2] = u.z; bv[i * 4 + 3] = u.w;
            }
        }

        // compute: 2 k16 steps
#pragma unroll
        for (int k16 = 0; k16 < 32; k16 += 16) {
            uint32_t ah[2][4], al[2][4];
#pragma unroll
            for (int mt = 0; mt < 2; mt++) {
                uint32_t ao = stg + a_lane_off + (uint32_t)((mt * 16 * A_STR + k16) * 2);
                ldsm_x4(ah[mt], ao + OFF_AH);
                ldsm_x4(al[mt], ao + OFF_AL);
            }
#pragma unroll
            for (int np = 0; np < 4; np++) {
                uint32_t bh[4], bl[4];
                uint32_t bo = stg + b_lane_off + (uint32_t)((k16 * B_STR + np * 16) * 2);
                ldsm_x4_t(bh, bo + OFF_BH);
                ldsm_x4_t(bl, bo + OFF_BL);
#pragma unroll
                for (int mt = 0; mt < 2; mt++) {
#pragma unroll
                    for (int nt = 0; nt < 2; nt++) {
                        float* d = acc[mt][np * 2 + nt];
                        mma_bf16(d, ah[mt], bh + nt * 2);
                        mma_bf16(d, al[mt], bh + nt * 2);
                        mma_bf16(d, ah[mt], bl + nt * 2);
                    }
                }
            }
        }
        __syncthreads();

        // store next chunk into other buffer
        if (c < 15) {
            char* nstg = smc + ((c + 1) & 1) * STAGE_BYTES;
            uint4 h0, l0, h1, l1;
            pack8(av, h0, l0); pack8(av + 8, h1, l1);
            char* abase = nstg + OFF_AH + (arow * A_STR + akh) * 2;
            *(uint4*)(abase)      = h0;  *(uint4*)(abase + 16) = h1;
            *(uint4*)(abase + OFF_AL) = l0;  *(uint4*)(abase + OFF_AL + 16) = l1;
            pack8(bv, h0, l0); pack8(bv + 8, h1, l1);
            char* bbase = nstg + OFF_BH + (brow * B_STR + bns) * 2;
            *(uint4*)(bbase)      = h0;  *(uint4*)(bbase + 16) = h1;
            *(uint4*)(bbase + OFF_BL - OFF_BH) = l0;
            *(uint4*)(bbase + OFF_BL - OFF_BH + 16) = l1;
            __syncthreads();
        }
    }

    // epilogue: write fp32
    const int g = lane >> 2;
    const int t = lane & 3;
#pragma unroll
    for (int mt = 0; mt < 2; mt++) {
#pragma unroll
        for (int np = 0; np < 4; np++) {
#pragma unroll
            for (int nt = 0; nt < 2; nt++) {
                const float* d = acc[mt][np * 2 + nt];
                int row = m0 + wm * 32 + mt * 16 + g;
                int col = n0 + wn * 64 + np * 16 + nt * 8 + t * 2;
                float* o0 = C + (size_t)row * 512 + col;
                o0[0] = d[0]; o0[1] = d[1];
                float* o1 = o0 + 8 * 512;
                o1[0] = d[2]; o1[1] = d[3];
            }
        }
    }
}

// ---------------------------------------------------------------------------
// Attention (unchanged, known good): 1 CTA per (b,t,h, 64-row l-chunk)
// ---------------------------------------------------------------------------
#define SM_Q   0
#define SM_KV  4352
#define SM_S   13056
#define ATTN_SMEM_BYTES (46080 * 4)

__global__ void __launch_bounds__(256) attn_kernel(
    const float* __restrict__ mask,
    const float* __restrict__ tau,
    const float* __restrict__ delta)
{
    extern __shared__ float smf[];
    float* sQT = smf + SM_Q;
    float* sKV = smf + SM_KV;
    float* sS  = smf + SM_S;

    const int tid  = threadIdx.x;
    const int tx   = tid & 15;
    const int ty   = tid >> 4;
    const int bth  = blockIdx.x;
    const int bt   = bth >> 3;
    const int h    = bth & 7;
    const int l0   = blockIdx.y * 64;

    const float tauv   = tau[0];
    const float deltav = delta[0];
    const float scale  = 0.125f;

    const float* Qbase = g_Q + ((size_t)bt * 512 + l0) * 512 + h * 64;
    const float* Kbase = g_K + (size_t)bt * 512 * 512 + h * 64;
    const float* Vbase = g_V + (size_t)bt * 512 * 512 + h * 64;

#pragma unroll
    for (int it = 0; it < 4; it++) {
        int idx = tid + it * 256;
        int r = idx >> 4, e4 = idx & 15;
        float4 v = *(const float4*)&Qbase[(size_t)r * 512 + e4 * 4];
        sQT[(e4 * 4 + 0) * 68 + r] = v.x;
        sQT[(e4 * 4 + 1) * 68 + r] = v.y;
        sQT[(e4 * 4 + 2) * 68 + r] = v.z;
        sQT[(e4 * 4 + 3) * 68 + r] = v.w;
    }

    for (int sc = 0; sc < 4; sc++) {
        __syncthreads();
#pragma unroll
        for (int it = 0; it < 8; it++) {
            int idx = tid + it * 256;
            int r = idx >> 4, e4 = idx & 15;
            float4 v = *(const float4*)&Kbase[(size_t)(sc * 128 + r) * 512 + e4 * 4];
            sKV[(e4 * 4 + 0) * 132 + r] = v.x;
            sKV[(e4 * 4 + 1) * 132 + r] = v.y;
            sKV[(e4 * 4 + 2) * 132 + r] = v.z;
            sKV[(e4 * 4 + 3) * 132 + r] = v.w;
        }
        __syncthreads();

        float acc[4][8];
#pragma unroll
        for (int i = 0; i < 4; i++)
#pragma unroll
            for (int j = 0; j < 8; j++) acc[i][j] = 0.f;

#pragma unroll 4
        for (int e = 0; e < 64; e++) {
            float4 q  = *(float4*)&sQT[e * 68 + ty * 4];
            float4 kA = *(float4*)&sKV[e * 132 + tx * 4];
            float4 kB = *(float4*)&sKV[e * 132 + 64 + tx * 4];
            float qv[4] = {q.x, q.y, q.z, q.w};
            float kv[8] = {kA.x, kA.y, kA.z, kA.w, kB.x, kB.y, kB.z, kB.w};
#pragma unroll
            for (int i = 0; i < 4; i++)
#pragma unroll
                for (int j = 0; j < 8; j++) acc[i][j] += qv[i] * kv[j];
        }

#pragma unroll
        for (int i = 0; i < 4; i++) {
            int li = ty * 4 + i;
            int gl = l0 + li;
            const float* mrow = mask + (size_t)gl * 512 + sc * 128;
            float4 mA = *(const float4*)&mrow[tx * 4];
            float4 mB = *(const float4*)&mrow[64 + tx * 4];
            float4 rA, rB;
            rA.x = (acc[i][0] * tauv + deltav) * scale * mA.x;
            rA.y = (acc[i][1] * tauv + deltav) * scale * mA.y;
            rA.z = (acc[i][2] * tauv + deltav) * scale * mA.z;
            rA.w = (acc[i][3] * tauv + deltav) * scale * mA.w;
            rB.x = (acc[i][4] * tauv + deltav) * scale * mB.x;
            rB.y = (acc[i][5] * tauv + deltav) * scale * mB.y;
            rB.z = (acc[i][6] * tauv + deltav) * scale * mB.z;
            rB.w = (acc[i][7] * tauv + deltav) * scale * mB.w;
            *(float4*)&sS[li * 516 + sc * 128 + tx * 4]      = rA;
            *(float4*)&sS[li * 516 + sc * 128 + 64 + tx * 4] = rB;
        }
    }
    __syncthreads();

    {
        const int lane = tid & 31;
        const int w    = tid >> 5;
        for (int r = 0; r < 8; r++) {
            int li = w * 8 + r;
            float* row = sS + li * 516;
            float4* row4 = (float4*)row;
            float m = -1e30f;
#pragma unroll
            for (int jj = lane; jj < 128; jj += 32) {
                float4 v = row4[jj];
                m = fmaxf(m, fmaxf(fmaxf(v.x, v.y), fmaxf(v.z, v.w)));
            }
#pragma unroll
            for (int o = 16; o; o >>= 1) m = fmaxf(m, __shfl_xor_sync(0xffffffffu, m, o));
            float sum = 0.f;
#pragma unroll
            for (int jj = lane; jj < 128; jj += 32) {
                float4 v = row4[jj];
                v.x = __expf(v.x - m);
                v.y = __expf(v.y - m);
                v.z = __expf(v.z - m);
                v.w = __expf(v.w - m);
                row4[jj] = v;
                sum += v.x + v.y + v.z + v.w;
            }
#pragma unroll
            for (int o = 16; o; o >>= 1) sum += __shfl_xor_sync(0xffffffffu, sum, o);
            float inv = 1.0f / sum;
#pragma unroll
            for (int jj = lane; jj < 128; jj += 32) {
                float4 v = row4[jj];
                v.x *= inv; v.y *= inv; v.z *= inv; v.w *= inv;
                row4[jj] = v;
            }
        }
    }
    __syncthreads();

    float o[4][4];
#pragma unroll
    for (int i = 0; i < 4; i++)
#pragma unroll
        for (int j = 0; j < 4; j++) o[i][j] = 0.f;

    for (int sc = 0; sc < 4; sc++) {
#pragma unroll
        for (int it = 0; it < 8; it++) {
            int idx = tid + it * 256;
            int r = idx >> 4, e4 = idx & 15;
            *(float4*)&sKV[r * 68 + e4 * 4] =
                *(const float4*)&Vbase[(size_t)(sc * 128 + r) * 512 + e4 * 4];
        }
        __syncthreads();

#pragma unroll 2
        for (int s4 = 0; s4 < 32; s4++) {
            float4 pp[4], vv[4];
#pragma unroll
            for (int i = 0; i < 4; i++)
                pp[i] = *(float4*)&sS[(ty * 4 + i) * 516 + sc * 128 + s4 * 4];
#pragma unroll
            for (int u = 0; u < 4; u++)
                vv[u] = *(float4*)&sKV[(s4 * 4 + u) * 68 + tx * 4];
#pragma unroll
            for (int i = 0; i < 4; i++) {
                float pv[4] = {pp[i].x, pp[i].y, pp[i].z, pp[i].w};
#pragma unroll
                for (int u = 0; u < 4; u++) {
                    o[i][0] += pv[u] * vv[u].x;
                    o[i][1] += pv[u] * vv[u].y;
                    o[i][2] += pv[u] * vv[u].z;
                    o[i][3] += pv[u] * vv[u].w;
                }
            }
        }
        __syncthreads();
    }

    float* dst = g_A + ((size_t)bth * 512 + l0) * 64;
#pragma unroll
    for (int i = 0; i < 4; i++) {
        float4 v = make_float4(o[i][0], o[i][1], o[i][2], o[i][3]);
        *(float4*)&dst[(ty * 4 + i) * 64 + tx * 4] = v;
    }
}

// ---------------------------------------------------------------------------
// Head reduction
// ---------------------------------------------------------------------------
__global__ void __launch_bounds__(256) reduce_heads(
    const float* __restrict__ w_head, float* __restrict__ out)
{
    int idx = blockIdx.x * 256 + threadIdx.x;
    int bt   = idx >> 15;
    int rest = idx & 32767;
    float s = 0.f;
#pragma unroll
    for (int h = 0; h < 8; h++)
        s += w_head[h] * g_A[(((size_t)bt * 8 + h) << 15) + rest];
    out[idx] = s;
}

// ---------------------------------------------------------------------------
extern "C" void kernel_launch(void* const* d_in, const int* in_sizes, int n_in,
                              void* d_out, int out_size)
{
    const float* queries = (const float*)d_in[0];
    const float* keys    = (const float*)d_in[1];
    const float* values  = (const float*)d_in[2];
    const float* mask    = (const float*)d_in[3];
    const float* Wq      = (const float*)d_in[4];
    const float* Wk      = (const float*)d_in[5];
    const float* Wv      = (const float*)d_in[6];
    const float* w_head  = (const float*)d_in[7];
    const float* tau     = (const float*)d_in[8];
    const float* delta   = (const float*)d_in[9];
    float* out = (float*)d_out;
    (void)in_sizes; (void)n_in; (void)out_size;

    cudaFuncSetAttribute(proj_mma,
                         cudaFuncAttributeMaxDynamicSharedMemorySize, PROJ_SMEM);
    cudaFuncSetAttribute(attn_kernel,
                         cudaFuncAttributeMaxDynamicSharedMemorySize, ATTN_SMEM_BYTES);

    // 1) projections on tensor cores (bf16 hi/lo split)
    {
        dim3 grid(4, 128, 3);     // n-tile, m-tile, projection
        proj_mma<<<grid, 256, PROJ_SMEM>>>(queries, keys, values, Wq, Wk, Wv);
    }

    // 2) attention
    {
        dim3 grid(256, 8);
        attn_kernel<<<grid, 256, ATTN_SMEM_BYTES>>>(mask, tau, delta);
    }

    // 3) weighted head sum
    reduce_heads<<<4096, 256>>>(w_head, out);
}

// round 4
// speedup vs baseline: 1.2447x; 1.0677x over previous
#include <cuda_runtime.h>
#include <cuda_bf16.h>
#include <stdint.h>
#include <math.h>

// Problem constants
#define BTN 32      // B*T
#define LLEN 512    // L
#define DDIM 512    // D
#define NH 8        // H
#define ED 64       // KD == VD
#define MROWS (BTN * LLEN)   // 16384

// Scratch (allocation-free rule -> device globals)
__device__ float g_Q[BTN * LLEN * DDIM];
__device__ float g_K[BTN * LLEN * DDIM];
__device__ float g_V[BTN * LLEN * DDIM];
__device__ float g_A[BTN * NH * LLEN * ED];

// ---------------------------------------------------------------------------
// mma.sync helpers (bf16 -> f32, m16n8k16) + ldmatrix
// ---------------------------------------------------------------------------
__device__ __forceinline__ uint32_t smem_u32(const void* p) {
    uint32_t a;
    asm("{ .reg .u64 t; cvta.to.shared.u64 t, %1; cvt.u32.u64 %0, t; }"
        : "=r"(a) : "l"(p));
    return a;
}

__device__ __forceinline__ void mma_bf16(float* d, const uint32_t* a, const uint32_t* b) {
    asm volatile(
        "mma.sync.aligned.m16n8k16.row.col.f32.bf16.bf16.f32 "
        "{%0,%1,%2,%3}, {%4,%5,%6,%7}, {%8,%9}, {%0,%1,%2,%3};"
        : "+f"(d[0]), "+f"(d[1]), "+f"(d[2]), "+f"(d[3])
        : "r"(a[0]), "r"(a[1]), "r"(a[2]), "r"(a[3]), "r"(b[0]), "r"(b[1]));
}

__device__ __forceinline__ void ldsm_x4(uint32_t* r, uint32_t addr) {
    asm volatile("ldmatrix.sync.aligned.m8n8.x4.shared.b16 {%0,%1,%2,%3}, [%4];"
                 : "=r"(r[0]), "=r"(r[1]), "=r"(r[2]), "=r"(r[3]) : "r"(addr));
}
__device__ __forceinline__ void ldsm_x4_t(uint32_t* r, uint32_t addr) {
    asm volatile("ldmatrix.sync.aligned.m8n8.x4.trans.shared.b16 {%0,%1,%2,%3}, [%4];"
                 : "=r"(r[0]), "=r"(r[1]), "=r"(r[2]), "=r"(r[3]) : "r"(addr));
}

// hi/lo bf16 split
__device__ __forceinline__ void split_bf16(float x, uint16_t& h, uint16_t& l) {
    __nv_bfloat16 hb = __float2bfloat16(x);
    float hf = __bfloat162float(hb);
    __nv_bfloat16 lb = __float2bfloat16(x - hf);
    h = __bfloat16_as_ushort(hb);
    l = __bfloat16_as_ushort(lb);
}

// pack 8 floats -> 8 hi halves (uint4) + 8 lo halves (uint4)
__device__ __forceinline__ void pack8(const float* xs, uint4& hi, uint4& lo) {
    uint16_t hs[8], ls[8];
#pragma unroll
    for (int j = 0; j < 8; j++) split_bf16(xs[j], hs[j], ls[j]);
    hi.x = (uint32_t)hs[0] | ((uint32_t)hs[1] << 16);
    hi.y = (uint32_t)hs[2] | ((uint32_t)hs[3] << 16);
    hi.z = (uint32_t)hs[4] | ((uint32_t)hs[5] << 16);
    hi.w = (uint32_t)hs[6] | ((uint32_t)hs[7] << 16);
    lo.x = (uint32_t)ls[0] | ((uint32_t)ls[1] << 16);
    lo.y = (uint32_t)ls[2] | ((uint32_t)ls[3] << 16);
    lo.z = (uint32_t)ls[4] | ((uint32_t)ls[5] << 16);
    lo.w = (uint32_t)ls[6] | ((uint32_t)ls[7] << 16);
}

// ---------------------------------------------------------------------------
// Projection GEMM (unchanged from R3, passing): mma.sync bf16 hi/lo split
// ---------------------------------------------------------------------------
#define A_STR 40
#define B_STR 136
#define OFF_AH 0
#define OFF_AL 10240
#define OFF_BH 20480
#define OFF_BL 29184
#define STAGE_BYTES 37888
#define PROJ_SMEM (2 * STAGE_BYTES)

__global__ void __launch_bounds__(256) proj_mma(
    const float* __restrict__ Xq, const float* __restrict__ Xk, const float* __restrict__ Xv,
    const float* __restrict__ Wq, const float* __restrict__ Wk, const float* __restrict__ Wv)
{
    extern __shared__ char smc[];
    const uint32_t sbase = smem_u32(smc);

    const int tid  = threadIdx.x;
    const int wid  = tid >> 5;
    const int lane = tid & 31;
    const int wm   = wid & 3;
    const int wn   = wid >> 2;

    const int p  = blockIdx.z;
    const int m0 = blockIdx.y * 128;
    const int n0 = blockIdx.x * 128;

    const float* X = (p == 0) ? Xq : (p == 1) ? Xk : Xv;
    const float* W = (p == 0) ? Wq : (p == 1) ? Wk : Wv;
    float*       C = (p == 0) ? g_Q : (p == 1) ? g_K : g_V;

    const int arow = tid >> 1;
    const int akh  = (tid & 1) * 16;
    const int brow = tid >> 3;
    const int bns  = (tid & 7) * 16;

    const float* aptr = X + (size_t)(m0 + arow) * 512 + akh;
    const float* bptr = W + (size_t)brow * 512 + n0 + bns;

    float acc[2][8][4];
#pragma unroll
    for (int i = 0; i < 2; i++)
#pragma unroll
        for (int j = 0; j < 8; j++)
#pragma unroll
            for (int q = 0; q < 4; q++) acc[i][j][q] = 0.f;

    const int lrow = lane & 15;
    const int lblk = lane >> 4;
    const uint32_t a_lane_off =
        (uint32_t)(((wm * 32 + lrow) * A_STR + lblk * 8) * 2);
    const uint32_t b_lane_off =
        (uint32_t)((lrow * B_STR + wn * 64 + lblk * 8) * 2);

    float av[16], bv[16];

    {
#pragma unroll
        for (int i = 0; i < 4; i++) {
            float4 t = *(const float4*)&aptr[i * 4];
            av[i * 4] = t.x; av[i * 4 + 1] = t.y; av[i * 4 + 2] = t.z; av[i * 4 + 3] = t.w;
            float4 u = *(const float4*)&bptr[i * 4];
            bv[i * 4] = u.x; bv[i * 4 + 1] = u.y; bv[i * 4 + 2] = u.z; bv[i * 4 + 3] = u.w;
        }
        uint4 h0, l0, h1, l1;
        pack8(av, h0, l0); pack8(av + 8, h1, l1);
        char* abase = smc + OFF_AH + (arow * A_STR + akh) * 2;
        *(uint4*)(abase)      = h0;  *(uint4*)(abase + 16) = h1;
        *(uint4*)(abase + OFF_AL) = l0;  *(uint4*)(abase + OFF_AL + 16) = l1;
        pack8(bv, h0, l0); pack8(bv + 8, h1, l1);
        char* bbase = smc + OFF_BH + (brow * B_STR + bns) * 2;
        *(uint4*)(bbase)      = h0;  *(uint4*)(bbase + 16) = h1;
        *(uint4*)(bbase + OFF_BL - OFF_BH) = l0;
        *(uint4*)(bbase + OFF_BL - OFF_BH + 16) = l1;
    }
    __syncthreads();

    for (int c = 0; c < 16; c++) {
        const int s = c & 1;
        const uint32_t stg = sbase + s * STAGE_BYTES;

        if (c < 15) {
            const int k0n = (c + 1) * 32;
            const float* ap = aptr + k0n;
            const float* bp = bptr + (size_t)k0n * 512;
#pragma unroll
            for (int i = 0; i < 4; i++) {
                float4 t = *(const float4*)&ap[i * 4];
                av[i * 4] = t.x; av[i * 4 + 1] = t.y; av[i * 4 + 2] = t.z; av[i * 4 + 3] = t.w;
                float4 u = *(const float4*)&bp[i * 4];
                bv[i * 4] = u.x; bv[i * 4 + 1] = u.y; bv[i * 4 + 2] = u.z; bv[i * 4 + 3] = u.w;
            }
        }

#pragma unroll
        for (int k16 = 0; k16 < 32; k16 += 16) {
            uint32_t ah[2][4], al[2][4];
#pragma unroll
            for (int mt = 0; mt < 2; mt++) {
                uint32_t ao = stg + a_lane_off + (uint32_t)((mt * 16 * A_STR + k16) * 2);
                ldsm_x4(ah[mt], ao + OFF_AH);
                ldsm_x4(al[mt], ao + OFF_AL);
            }
#pragma unroll
            for (int np = 0; np < 4; np++) {
                uint32_t bh[4], bl[4];
                uint32_t bo = stg + b_lane_off + (uint32_t)((k16 * B_STR + np * 16) * 2);
                ldsm_x4_t(bh, bo + OFF_BH);
                ldsm_x4_t(bl, bo + OFF_BL);
#pragma unroll
                for (int mt = 0; mt < 2; mt++) {
#pragma unroll
                    for (int nt = 0; nt < 2; nt++) {
                        float* d = acc[mt][np * 2 + nt];
                        mma_bf16(d, ah[mt], bh + nt * 2);
                        mma_bf16(d, al[mt], bh + nt * 2);
                        mma_bf16(d, ah[mt], bl + nt * 2);
                    }
                }
            }
        }
        __syncthreads();

        if (c < 15) {
            char* nstg = smc + ((c + 1) & 1) * STAGE_BYTES;
            uint4 h0, l0, h1, l1;
            pack8(av, h0, l0); pack8(av + 8, h1, l1);
            char* abase = nstg + OFF_AH + (arow * A_STR + akh) * 2;
            *(uint4*)(abase)      = h0;  *(uint4*)(abase + 16) = h1;
            *(uint4*)(abase + OFF_AL) = l0;  *(uint4*)(abase + OFF_AL + 16) = l1;
            pack8(bv, h0, l0); pack8(bv + 8, h1, l1);
            char* bbase = nstg + OFF_BH + (brow * B_STR + bns) * 2;
            *(uint4*)(bbase)      = h0;  *(uint4*)(bbase + 16) = h1;
            *(uint4*)(bbase + OFF_BL - OFF_BH) = l0;
            *(uint4*)(bbase + OFF_BL - OFF_BH + 16) = l1;
            __syncthreads();
        }
    }

    const int g = lane >> 2;
    const int t = lane & 3;
#pragma unroll
    for (int mt = 0; mt < 2; mt++) {
#pragma unroll
        for (int np = 0; np < 4; np++) {
#pragma unroll
            for (int nt = 0; nt < 2; nt++) {
                const float* d = acc[mt][np * 2 + nt];
                int row = m0 + wm * 32 + mt * 16 + g;
                int col = n0 + wn * 64 + np * 16 + nt * 8 + t * 2;
                float* o0 = C + (size_t)row * 512 + col;
                o0[0] = d[0]; o0[1] = d[1];
                float* o1 = o0 + 8 * 512;
                o1[0] = d[2]; o1[1] = d[3];
            }
        }
    }
}

// ---------------------------------------------------------------------------
// Attention on tensor cores: 1 CTA per (b,t,h, 64-row l-chunk), 256 threads.
// QK^T and P@V via mma.sync bf16 hi/lo (3-term); softmax fp32 in smem strip.
// smem (bytes):
//   [0]       sS   64 x 516 fp32                 132096
//   [132096]  sQh  64 x 72 bf16                    9216
//   [141312]  sQl                                  9216
//   [150528]  phase region (71680):
//      QK phase: sKh(18432) sKl(18432)            (128 x 72 bf16 each)
//      PV phase: sPh(17408) sPl(17408) sVh(18432) sVl(18432)
// total 222208
// ---------------------------------------------------------------------------
#define ATT_SS   0
#define ATT_QH   132096
#define ATT_QL   141312
#define ATT_KH   150528
#define ATT_KL   168960
#define ATT_PH   150528
#define ATT_PL   167936
#define ATT_VH   185344
#define ATT_VL   203776
#define ATT_SMEM 222208

__global__ void __launch_bounds__(256) attn_mma(
    const float* __restrict__ mask,
    const float* __restrict__ tau,
    const float* __restrict__ delta)
{
    extern __shared__ char smc[];
    const uint32_t sb = smem_u32(smc);
    float* sS = (float*)(smc + ATT_SS);

    const int tid  = threadIdx.x;
    const int wid  = tid >> 5;
    const int lane = tid & 31;
    const int wm   = wid & 3;       // 4 m-warps x 16 rows
    const int wn   = wid >> 2;      // 2 n-warps

    const int bth = blockIdx.x;
    const int bt  = bth >> 3;
    const int h   = bth & 7;
    const int l0  = blockIdx.y * 64;

    const float tauv   = tau[0];
    const float deltav = delta[0];
    const float scale  = 0.125f;

    const float* Qg = g_Q + (size_t)bt * 512 * 512 + h * 64;
    const float* Kg = g_K + (size_t)bt * 512 * 512 + h * 64;
    const float* Vg = g_V + (size_t)bt * 512 * 512 + h * 64;

    // ---- convert Q chunk (64 x 64) to bf16 hi/lo, pitch 72 halves ----
    {
        const int row = tid >> 2, c = (tid & 3) * 16;
        const float* src = Qg + (size_t)(l0 + row) * 512 + c;
        float xs[16];
#pragma unroll
        for (int i = 0; i < 4; i++) {
            float4 t = *(const float4*)&src[i * 4];
            xs[i * 4] = t.x; xs[i * 4 + 1] = t.y; xs[i * 4 + 2] = t.z; xs[i * 4 + 3] = t.w;
        }
        uint4 h0, lo0, h1, lo1;
        pack8(xs, h0, lo0); pack8(xs + 8, h1, lo1);
        char* qh = smc + ATT_QH + (row * 72 + c) * 2;
        char* ql = smc + ATT_QL + (row * 72 + c) * 2;
        *(uint4*)(qh) = h0; *(uint4*)(qh + 16) = h1;
        *(uint4*)(ql) = lo0; *(uint4*)(ql + 16) = lo1;
    }

    // fragment lane offsets
    const int arow = lane & 15;
    const int acol = (lane >> 4) * 8;
    const int krow = (lane & 7) | ((lane & 16) >> 1);  // non-trans B rows
    const int kcol = lane & 8;
    const int grp  = lane >> 2;
    const int tc   = (lane & 3) * 2;

    // ================= QK^T =================
    for (int sc = 0; sc < 4; sc++) {
        __syncthreads();
        // convert K tile (128 x 64), pitch 72
        {
            const int s = tid >> 1, c = (tid & 1) * 32;
            const float* src = Kg + (size_t)(sc * 128 + s) * 512 + c;
            float xs[32];
#pragma unroll
            for (int i = 0; i < 8; i++) {
                float4 t = *(const float4*)&src[i * 4];
                xs[i * 4] = t.x; xs[i * 4 + 1] = t.y; xs[i * 4 + 2] = t.z; xs[i * 4 + 3] = t.w;
            }
            char* kh = smc + ATT_KH + (s * 72 + c) * 2;
            char* kl = smc + ATT_KL + (s * 72 + c) * 2;
#pragma unroll
            for (int q = 0; q < 4; q++) {
                uint4 hh, ll;
                pack8(xs + q * 8, hh, ll);
                *(uint4*)(kh + q * 16) = hh;
                *(uint4*)(kl + q * 16) = ll;
            }
        }
        __syncthreads();

        float acc[8][4];
#pragma unroll
        for (int j = 0; j < 8; j++)
#pragma unroll
            for (int q = 0; q < 4; q++) acc[j][q] = 0.f;

#pragma unroll
        for (int k16 = 0; k16 < 64; k16 += 16) {
            uint32_t ah[4], al[4];
            uint32_t qoff = (uint32_t)(((wm * 16 + arow) * 72 + acol + k16) * 2);
            ldsm_x4(ah, sb + ATT_QH + qoff);
            ldsm_x4(al, sb + ATT_QL + qoff);
#pragma unroll
            for (int np = 0; np < 4; np++) {
                uint32_t bh[4], bl[4];
                uint32_t koff = (uint32_t)((((wn * 64 + np * 16) + krow) * 72 + kcol + k16) * 2);
                ldsm_x4(bh, sb + ATT_KH + koff);
                ldsm_x4(bl, sb + ATT_KL + koff);
#pragma unroll
                for (int nt = 0; nt < 2; nt++) {
                    float* d = acc[np * 2 + nt];
                    mma_bf16(d, ah, bh + nt * 2);
                    mma_bf16(d, al, bh + nt * 2);
                    mma_bf16(d, ah, bl + nt * 2);
                }
            }
        }

        // scale + mask + store scores
#pragma unroll
        for (int j = 0; j < 8; j++) {
            const int col = sc * 128 + wn * 64 + j * 8 + tc;
            const int lr0 = wm * 16 + grp;
            const int lr1 = lr0 + 8;
            float2 m0 = *(const float2*)&mask[(size_t)(l0 + lr0) * 512 + col];
            float2 m1 = *(const float2*)&mask[(size_t)(l0 + lr1) * 512 + col];
            const float* d = acc[j];
            float2 r0, r1;
            r0.x = (d[0] * tauv + deltav) * scale * m0.x;
            r0.y = (d[1] * tauv + deltav) * scale * m0.y;
            r1.x = (d[2] * tauv + deltav) * scale * m1.x;
            r1.y = (d[3] * tauv + deltav) * scale * m1.y;
            *(float2*)&sS[lr0 * 516 + col] = r0;
            *(float2*)&sS[lr1 * 516 + col] = r1;
        }
    }
    __syncthreads();

    // ================= softmax (fp32) =================
    {
        const int ln = tid & 31;
        const int w  = tid >> 5;
        for (int r = 0; r < 8; r++) {
            int li = w * 8 + r;
            float4* row4 = (float4*)(sS + li * 516);
            float m = -1e30f;
#pragma unroll
            for (int jj = ln; jj < 128; jj += 32) {
                float4 v = row4[jj];
                m = fmaxf(m, fmaxf(fmaxf(v.x, v.y), fmaxf(v.z, v.w)));
            }
#pragma unroll
            for (int o = 16; o; o >>= 1) m = fmaxf(m, __shfl_xor_sync(0xffffffffu, m, o));
            float sum = 0.f;
#pragma unroll
            for (int jj = ln; jj < 128; jj += 32) {
                float4 v = row4[jj];
                v.x = __expf(v.x - m); v.y = __expf(v.y - m);
                v.z = __expf(v.z - m); v.w = __expf(v.w - m);
                row4[jj] = v;
                sum += v.x + v.y + v.z + v.w;
            }
#pragma unroll
            for (int o = 16; o; o >>= 1) sum += __shfl_xor_sync(0xffffffffu, sum, o);
            float inv = 1.0f / sum;
#pragma unroll
            for (int jj = ln; jj < 128; jj += 32) {
                float4 v = row4[jj];
                v.x *= inv; v.y *= inv; v.z *= inv; v.w *= inv;
                row4[jj] = v;
            }
        }
    }
    __syncthreads();

    // ================= P @ V =================
    float acc2[4][4];
#pragma unroll
    for (int j = 0; j < 4; j++)
#pragma unroll
        for (int q = 0; q < 4; q++) acc2[j][q] = 0.f;

    for (int sc = 0; sc < 4; sc++) {
        if (sc) __syncthreads();
        // convert P chunk (64 x 128), pitch 136
        {
            const int row = tid >> 2, c = (tid & 3) * 32;
            const float* src = sS + row * 516 + sc * 128 + c;
            float xs[32];
#pragma unroll
            for (int i = 0; i < 8; i++) {
                float4 t = *(const float4*)&src[i * 4];
                xs[i * 4] = t.x; xs[i * 4 + 1] = t.y; xs[i * 4 + 2] = t.z; xs[i * 4 + 3] = t.w;
            }
            char* ph = smc + ATT_PH + (row * 136 + c) * 2;
            char* pl = smc + ATT_PL + (row * 136 + c) * 2;
#pragma unroll
            for (int q = 0; q < 4; q++) {
                uint4 hh, ll;
                pack8(xs + q * 8, hh, ll);
                *(uint4*)(ph + q * 16) = hh;
                *(uint4*)(pl + q * 16) = ll;
            }
        }
        // convert V tile (128 x 64), pitch 72
        {
            const int s = tid >> 1, c = (tid & 1) * 32;
            const float* src = Vg + (size_t)(sc * 128 + s) * 512 + c;
            float xs[32];
#pragma unroll
            for (int i = 0; i < 8; i++) {
                float4 t = *(const float4*)&src[i * 4];
                xs[i * 4] = t.x; xs[i * 4 + 1] = t.y; xs[i * 4 + 2] = t.z; xs[i * 4 + 3] = t.w;
            }
            char* vh = smc + ATT_VH + (s * 72 + c) * 2;
            char* vl = smc + ATT_VL + (s * 72 + c) * 2;
#pragma unroll
            for (int q = 0; q < 4; q++) {
                uint4 hh, ll;
                pack8(xs + q * 8, hh, ll);
                *(uint4*)(vh + q * 16) = hh;
                *(uint4*)(vl + q * 16) = ll;
            }
        }
        __syncthreads();

#pragma unroll
        for (int ks = 0; ks < 8; ks++) {
            const int k16 = ks * 16;
            uint32_t ph[4], pl[4];
            uint32_t poff = (uint32_t)(((wm * 16 + arow) * 136 + acol + k16) * 2);
            ldsm_x4(ph, sb + ATT_PH + poff);
            ldsm_x4(pl, sb + ATT_PL + poff);
#pragma unroll
            for (int np = 0; np < 2; np++) {
                uint32_t vh[4], vl[4];
                uint32_t voff = (uint32_t)(((k16 + arow) * 72 + wn * 32 + np * 16 + acol) * 2);
                ldsm_x4_t(vh, sb + ATT_VH + voff);
                ldsm_x4_t(vl, sb + ATT_VL + voff);
#pragma unroll
                for (int nt = 0; nt < 2; nt++) {
                    float* d = acc2[np * 2 + nt];
                    mma_bf16(d, ph, vh + nt * 2);
                    mma_bf16(d, pl, vh + nt * 2);
                    mma_bf16(d, ph, vl + nt * 2);
                }
            }
        }
    }

    // ---- write per-head attention output ----
#pragma unroll
    for (int np = 0; np < 2; np++) {
#pragma unroll
        for (int nt = 0; nt < 2; nt++) {
            const float* d = acc2[np * 2 + nt];
            const int col = wn * 32 + np * 16 + nt * 8 + tc;
            const int row0 = wm * 16 + grp;
            float* dst = g_A + ((size_t)bth * 512 + l0 + row0) * 64 + col;
            *(float2*)dst = make_float2(d[0], d[1]);
            *(float2*)(dst + 8 * 64) = make_float2(d[2], d[3]);
        }
    }
}

// ---------------------------------------------------------------------------
// Head reduction
// ---------------------------------------------------------------------------
__global__ void __launch_bounds__(256) reduce_heads(
    const float* __restrict__ w_head, float* __restrict__ out)
{
    int idx = blockIdx.x * 256 + threadIdx.x;
    int bt   = idx >> 15;
    int rest = idx & 32767;
    float s = 0.f;
#pragma unroll
    for (int h = 0; h < 8; h++)
        s += w_head[h] * g_A[(((size_t)bt * 8 + h) << 15) + rest];
    out[idx] = s;
}

// ---------------------------------------------------------------------------
extern "C" void kernel_launch(void* const* d_in, const int* in_sizes, int n_in,
                              void* d_out, int out_size)
{
    const float* queries = (const float*)d_in[0];
    const float* keys    = (const float*)d_in[1];
    const float* values  = (const float*)d_in[2];
    const float* mask    = (const float*)d_in[3];
    const float* Wq      = (const float*)d_in[4];
    const float* Wk      = (const float*)d_in[5];
    const float* Wv      = (const float*)d_in[6];
    const float* w_head  = (const float*)d_in[7];
    const float* tau     = (const float*)d_in[8];
    const float* delta   = (const float*)d_in[9];
    float* out = (float*)d_out;
    (void)in_sizes; (void)n_in; (void)out_size;

    cudaFuncSetAttribute(proj_mma,
                         cudaFuncAttributeMaxDynamicSharedMemorySize, PROJ_SMEM);
    cudaFuncSetAttribute(attn_mma,
                         cudaFuncAttributeMaxDynamicSharedMemorySize, ATT_SMEM);

    // 1) projections on tensor cores
    {
        dim3 grid(4, 128, 3);
        proj_mma<<<grid, 256, PROJ_SMEM>>>(queries, keys, values, Wq, Wk, Wv);
    }

    // 2) attention on tensor cores
    {
        dim3 grid(256, 8);
        attn_mma<<<grid, 256, ATT_SMEM>>>(mask, tau, delta);
    }

    // 3) weighted head sum
    reduce_heads<<<4096, 256>>>(w_head, out);
}

// round 5
// speedup vs baseline: 2.1010x; 1.6879x over previous
#include <cuda_runtime.h>
#include <cuda_bf16.h>
#include <stdint.h>
#include <math.h>

// Problem constants
#define BTN 32      // B*T
#define LLEN 512    // L
#define DDIM 512    // D
#define NH 8        // H
#define ED 64       // KD == VD
#define MROWS (BTN * LLEN)   // 16384

// Scratch: pre-split bf16 hi/lo Q/K/V  [bt][l][h*64+e], plus attn out
__device__ __align__(16) __nv_bfloat16 g_Qh[MROWS * DDIM];
__device__ __align__(16) __nv_bfloat16 g_Ql[MROWS * DDIM];
__device__ __align__(16) __nv_bfloat16 g_Kh[MROWS * DDIM];
__device__ __align__(16) __nv_bfloat16 g_Kl[MROWS * DDIM];
__device__ __align__(16) __nv_bfloat16 g_Vh[MROWS * DDIM];
__device__ __align__(16) __nv_bfloat16 g_Vl[MROWS * DDIM];
__device__ float g_A[BTN * NH * LLEN * ED];

// ---------------------------------------------------------------------------
// helpers
// ---------------------------------------------------------------------------
__device__ __forceinline__ uint32_t smem_u32(const void* p) {
    uint32_t a;
    asm("{ .reg .u64 t; cvta.to.shared.u64 t, %1; cvt.u32.u64 %0, t; }"
        : "=r"(a) : "l"(p));
    return a;
}

__device__ __forceinline__ void mma_bf16(float* d, const uint32_t* a, const uint32_t* b) {
    asm volatile(
        "mma.sync.aligned.m16n8k16.row.col.f32.bf16.bf16.f32 "
        "{%0,%1,%2,%3}, {%4,%5,%6,%7}, {%8,%9}, {%0,%1,%2,%3};"
        : "+f"(d[0]), "+f"(d[1]), "+f"(d[2]), "+f"(d[3])
        : "r"(a[0]), "r"(a[1]), "r"(a[2]), "r"(a[3]), "r"(b[0]), "r"(b[1]));
}

__device__ __forceinline__ void ldsm_x4(uint32_t* r, uint32_t addr) {
    asm volatile("ldmatrix.sync.aligned.m8n8.x4.shared.b16 {%0,%1,%2,%3}, [%4];"
                 : "=r"(r[0]), "=r"(r[1]), "=r"(r[2]), "=r"(r[3]) : "r"(addr));
}
__device__ __forceinline__ void ldsm_x4_t(uint32_t* r, uint32_t addr) {
    asm volatile("ldmatrix.sync.aligned.m8n8.x4.trans.shared.b16 {%0,%1,%2,%3}, [%4];"
                 : "=r"(r[0]), "=r"(r[1]), "=r"(r[2]), "=r"(r[3]) : "r"(addr));
}

#define CP16(dst, src) \
    asm volatile("cp.async.cg.shared.global [%0], [%1], 16;" :: "r"(dst), "l"(src))
#define CP_COMMIT() asm volatile("cp.async.commit_group;" ::: "memory")
#define CP_WAIT0()  asm volatile("cp.async.wait_group 0;" ::: "memory")

__device__ __forceinline__ void split_bf16(float x, uint16_t& h, uint16_t& l) {
    __nv_bfloat16 hb = __float2bfloat16(x);
    float hf = __bfloat162float(hb);
    __nv_bfloat16 lb = __float2bfloat16(x - hf);
    h = __bfloat16_as_ushort(hb);
    l = __bfloat16_as_ushort(lb);
}

__device__ __forceinline__ void pack8(const float* xs, uint4& hi, uint4& lo) {
    uint16_t hs[8], ls[8];
#pragma unroll
    for (int j = 0; j < 8; j++) split_bf16(xs[j], hs[j], ls[j]);
    hi.x = (uint32_t)hs[0] | ((uint32_t)hs[1] << 16);
    hi.y = (uint32_t)hs[2] | ((uint32_t)hs[3] << 16);
    hi.z = (uint32_t)hs[4] | ((uint32_t)hs[5] << 16);
    hi.w = (uint32_t)hs[6] | ((uint32_t)hs[7] << 16);
    lo.x = (uint32_t)ls[0] | ((uint32_t)ls[1] << 16);
    lo.y = (uint32_t)ls[2] | ((uint32_t)ls[3] << 16);
    lo.z = (uint32_t)ls[4] | ((uint32_t)ls[5] << 16);
    lo.w = (uint32_t)ls[6] | ((uint32_t)ls[7] << 16);
}

// pack two fp32 -> bf16x2 (a -> lower half, b -> upper half)
__device__ __forceinline__ uint32_t pk2(float a, float b) {
    uint32_t r;
    asm("cvt.rn.bf16x2.f32 %0, %1, %2;" : "=r"(r) : "f"(b), "f"(a));
    return r;
}
__device__ __forceinline__ float rlo(float x) {
    return x - __bfloat162float(__float2bfloat16(x));
}

// ---------------------------------------------------------------------------
// Projection GEMM (R3/R4 core, epilogue writes bf16 hi/lo split directly)
// ---------------------------------------------------------------------------
#define A_STR 40
#define B_STR 136
#define OFF_AH 0
#define OFF_AL 10240
#define OFF_BH 20480
#define OFF_BL 29184
#define STAGE_BYTES 37888
#define PROJ_SMEM (2 * STAGE_BYTES)

__global__ void __launch_bounds__(256) proj_mma(
    const float* __restrict__ Xq, const float* __restrict__ Xk, const float* __restrict__ Xv,
    const float* __restrict__ Wq, const float* __restrict__ Wk, const float* __restrict__ Wv)
{
    extern __shared__ char smc[];
    const uint32_t sbase = smem_u32(smc);

    const int tid  = threadIdx.x;
    const int wid  = tid >> 5;
    const int lane = tid & 31;
    const int wm   = wid & 3;
    const int wn   = wid >> 2;

    const int p  = blockIdx.z;
    const int m0 = blockIdx.y * 128;
    const int n0 = blockIdx.x * 128;

    const float* X = (p == 0) ? Xq : (p == 1) ? Xk : Xv;
    const float* W = (p == 0) ? Wq : (p == 1) ? Wk : Wv;
    __nv_bfloat16* Ch = (p == 0) ? g_Qh : (p == 1) ? g_Kh : g_Vh;
    __nv_bfloat16* Cl = (p == 0) ? g_Ql : (p == 1) ? g_Kl : g_Vl;

    const int arow = tid >> 1;
    const int akh  = (tid & 1) * 16;
    const int brow = tid >> 3;
    const int bns  = (tid & 7) * 16;

    const float* aptr = X + (size_t)(m0 + arow) * 512 + akh;
    const float* bptr = W + (size_t)brow * 512 + n0 + bns;

    float acc[2][8][4];
#pragma unroll
    for (int i = 0; i < 2; i++)
#pragma unroll
        for (int j = 0; j < 8; j++)
#pragma unroll
            for (int q = 0; q < 4; q++) acc[i][j][q] = 0.f;

    const int lrow = lane & 15;
    const int lblk = lane >> 4;
    const uint32_t a_lane_off = (uint32_t)(((wm * 32 + lrow) * A_STR + lblk * 8) * 2);
    const uint32_t b_lane_off = (uint32_t)((lrow * B_STR + wn * 64 + lblk * 8) * 2);

    float av[16], bv[16];
    {
#pragma unroll
        for (int i = 0; i < 4; i++) {
            float4 t = *(const float4*)&aptr[i * 4];
            av[i * 4] = t.x; av[i * 4 + 1] = t.y; av[i * 4 + 2] = t.z; av[i * 4 + 3] = t.w;
            float4 u = *(const float4*)&bptr[i * 4];
            bv[i * 4] = u.x; bv[i * 4 + 1] = u.y; bv[i * 4 + 2] = u.z; bv[i * 4 + 3] = u.w;
        }
        uint4 h0, l0, h1, l1;
        pack8(av, h0, l0); pack8(av + 8, h1, l1);
        char* abase = smc + OFF_AH + (arow * A_STR + akh) * 2;
        *(uint4*)(abase)      = h0;  *(uint4*)(abase + 16) = h1;
        *(uint4*)(abase + OFF_AL) = l0;  *(uint4*)(abase + OFF_AL + 16) = l1;
        pack8(bv, h0, l0); pack8(bv + 8, h1, l1);
        char* bbase = smc + OFF_BH + (brow * B_STR + bns) * 2;
        *(uint4*)(bbase)      = h0;  *(uint4*)(bbase + 16) = h1;
        *(uint4*)(bbase + OFF_BL - OFF_BH) = l0;
        *(uint4*)(bbase + OFF_BL - OFF_BH + 16) = l1;
    }
    __syncthreads();

    for (int c = 0; c < 16; c++) {
        const int s = c & 1;
        const uint32_t stg = sbase + s * STAGE_BYTES;

        if (c < 15) {
            const int k0n = (c + 1) * 32;
            const float* ap = aptr + k0n;
            const float* bp = bptr + (size_t)k0n * 512;
#pragma unroll
            for (int i = 0; i < 4; i++) {
                float4 t = *(const float4*)&ap[i * 4];
                av[i * 4] = t.x; av[i * 4 + 1] = t.y; av[i * 4 + 2] = t.z; av[i * 4 + 3] = t.w;
                float4 u = *(const float4*)&bp[i * 4];
                bv[i * 4] = u.x; bv[i * 4 + 1] = u.y; bv[i * 4 + 2] = u.z; bv[i * 4 + 3] = u.w;
            }
        }

#pragma unroll
        for (int k16 = 0; k16 < 32; k16 += 16) {
            uint32_t ah[2][4], al[2][4];
#pragma unroll
            for (int mt = 0; mt < 2; mt++) {
                uint32_t ao = stg + a_lane_off + (uint32_t)((mt * 16 * A_STR + k16) * 2);
                ldsm_x4(ah[mt], ao + OFF_AH);
                ldsm_x4(al[mt], ao + OFF_AL);
            }
#pragma unroll
            for (int np = 0; np < 4; np++) {
                uint32_t bh[4], bl[4];
                uint32_t bo = stg + b_lane_off + (uint32_t)((k16 * B_STR + np * 16) * 2);
                ldsm_x4_t(bh, bo + OFF_BH);
                ldsm_x4_t(bl, bo + OFF_BL);
#pragma unroll
                for (int mt = 0; mt < 2; mt++) {
#pragma unroll
                    for (int nt = 0; nt < 2; nt++) {
                        float* d = acc[mt][np * 2 + nt];
                        mma_bf16(d, ah[mt], bh + nt * 2);
                        mma_bf16(d, al[mt], bh + nt * 2);
                        mma_bf16(d, ah[mt], bl + nt * 2);
                    }
                }
            }
        }
        __syncthreads();

        if (c < 15) {
            char* nstg = smc + ((c + 1) & 1) * STAGE_BYTES;
            uint4 h0, l0, h1, l1;
            pack8(av, h0, l0); pack8(av + 8, h1, l1);
            char* abase = nstg + OFF_AH + (arow * A_STR + akh) * 2;
            *(uint4*)(abase)      = h0;  *(uint4*)(abase + 16) = h1;
            *(uint4*)(abase + OFF_AL) = l0;  *(uint4*)(abase + OFF_AL + 16) = l1;
            pack8(bv, h0, l0); pack8(bv + 8, h1, l1);
            char* bbase = nstg + OFF_BH + (brow * B_STR + bns) * 2;
            *(uint4*)(bbase)      = h0;  *(uint4*)(bbase + 16) = h1;
            *(uint4*)(bbase + OFF_BL - OFF_BH) = l0;
            *(uint4*)(bbase + OFF_BL - OFF_BH + 16) = l1;
            __syncthreads();
        }
    }

    // epilogue: split fp32 accumulators into bf16 hi/lo pairs
    const int g = lane >> 2;
    const int t = lane & 3;
#pragma unroll
    for (int mt = 0; mt < 2; mt++) {
#pragma unroll
        for (int np = 0; np < 4; np++) {
#pragma unroll
            for (int nt = 0; nt < 2; nt++) {
                const float* d = acc[mt][np * 2 + nt];
                int row = m0 + wm * 32 + mt * 16 + g;
                int col = n0 + wn * 64 + np * 16 + nt * 8 + t * 2;
                uint16_t h0, l0, h1, l1;
                split_bf16(d[0], h0, l0);
                split_bf16(d[1], h1, l1);
                *(uint32_t*)(Ch + (size_t)row * 512 + col) = (uint32_t)h0 | ((uint32_t)h1 << 16);
                *(uint32_t*)(Cl + (size_t)row * 512 + col) = (uint32_t)l0 | ((uint32_t)l1 << 16);
                split_bf16(d[2], h0, l0);
                split_bf16(d[3], h1, l1);
                *(uint32_t*)(Ch + (size_t)(row + 8) * 512 + col) = (uint32_t)h0 | ((uint32_t)h1 << 16);
                *(uint32_t*)(Cl + (size_t)(row + 8) * 512 + col) = (uint32_t)l0 | ((uint32_t)l1 << 16);
            }
        }
    }
}

// ---------------------------------------------------------------------------
// Flash attention: 1 CTA (128 thr, 4 warps) per (bth, 64-row l-chunk).
// Online softmax; Q in regs; K/V bf16 hi/lo double-buffered via cp.async.
// smem: QH 9216 | QL 9216 | 2 stages x {KH,KL,VH,VL} each 9216.  total 92160.
// ---------------------------------------------------------------------------
#define AQH 0
#define AQL 9216
#define AST 18432
#define STG 36864
#define ATT_SMEM 92160

__global__ void __launch_bounds__(128, 2) attn_flash(
    const float* __restrict__ mask,
    const float* __restrict__ tau,
    const float* __restrict__ delta)
{
    extern __shared__ char smc[];
    const uint32_t sb = smem_u32(smc);

    const int tid  = threadIdx.x;
    const int wid  = tid >> 5;
    const int lane = tid & 31;
    const int wm   = wid;                  // 4 warps x 16 rows

    const int bth = blockIdx.x;
    const int bt  = bth >> 3;
    const int h   = bth & 7;
    const int l0  = blockIdx.y * 64;

    const float tauv   = tau[0];
    const float deltav = delta[0];
    const float scale  = 0.125f;

    const size_t hb = (size_t)bt * 512 * 512 + h * 64;
    const __nv_bfloat16* Kh_ = g_Kh + hb;
    const __nv_bfloat16* Kl_ = g_Kl + hb;
    const __nv_bfloat16* Vh_ = g_Vh + hb;
    const __nv_bfloat16* Vl_ = g_Vl + hb;

    // fragment lane geometry
    const int arow = lane & 15;
    const int acol = (lane >> 4) * 8;
    const int krow = (lane & 7) | ((lane & 16) >> 1);
    const int kcol = lane & 8;
    const int g    = lane >> 2;
    const int tc   = (lane & 3) * 2;

    // ---- issue cp.async for stage 0 (s-tile 0) ----
    {
        const int s_row0 = 0;
#pragma unroll
        for (int i = 0; i < 4; i++) {
            int q = tid + i * 128;
            int row = q >> 3, c16 = q & 7;
            size_t gs = (size_t)(s_row0 + row) * 512 + c16 * 8;
            uint32_t dr = sb + AST + row * 144 + c16 * 16;
            CP16(dr +     0, Kh_ + gs);
            CP16(dr +  9216, Kl_ + gs);
            CP16(dr + 18432, Vh_ + gs);
            CP16(dr + 27648, Vl_ + gs);
        }
        CP_COMMIT();
    }

    // ---- stage Q (plain copy, bf16 hi/lo, pitch 72 halves) ----
    {
        const __nv_bfloat16* Qh_ = g_Qh + hb + (size_t)l0 * 512;
        const __nv_bfloat16* Ql_ = g_Ql + hb + (size_t)l0 * 512;
#pragma unroll
        for (int i = 0; i < 8; i++) {
            int arr = i >> 2;
            int q = tid + (i & 3) * 128;
            int row = q >> 3, c16 = q & 7;
            size_t gs = (size_t)row * 512 + c16 * 8;
            const __nv_bfloat16* src = arr ? Ql_ : Qh_;
            *(uint4*)(smc + (arr ? AQL : AQH) + row * 144 + c16 * 16) =
                *(const uint4*)(src + gs);
        }
    }
    __syncthreads();

    // ---- Q fragments into registers ----
    uint32_t qfh[4][4], qfl[4][4];
#pragma unroll
    for (int kk = 0; kk < 4; kk++) {
        uint32_t qoff = (uint32_t)(((wm * 16 + arow) * 72 + acol + kk * 16) * 2);
        ldsm_x4(qfh[kk], sb + AQH + qoff);
        ldsm_x4(qfl[kk], sb + AQL + qoff);
    }

    // online state
    float O[8][4];
#pragma unroll
    for (int j = 0; j < 8; j++)
#pragma unroll
        for (int q = 0; q < 4; q++) O[j][q] = 0.f;
    float m_g = -1e30f, m_h = -1e30f, l_g = 0.f, l_h = 0.f;

    const float* mrow0 = mask + (size_t)(l0 + wm * 16 + g) * 512;
    const float* mrow1 = mrow0 + 8 * 512;

    for (int sc = 0; sc < 8; sc++) {
        CP_WAIT0();
        __syncthreads();
        const uint32_t stoff = sb + AST + (sc & 1) * STG;

        // prefetch next s-tile
        if (sc < 7) {
            const int s_row0 = (sc + 1) * 64;
            const uint32_t nst = sb + AST + ((sc + 1) & 1) * STG;
#pragma unroll
            for (int i = 0; i < 4; i++) {
                int q = tid + i * 128;
                int row = q >> 3, c16 = q & 7;
                size_t gs = (size_t)(s_row0 + row) * 512 + c16 * 8;
                uint32_t dr = nst + row * 144 + c16 * 16;
                CP16(dr +     0, Kh_ + gs);
                CP16(dr +  9216, Kl_ + gs);
                CP16(dr + 18432, Vh_ + gs);
                CP16(dr + 27648, Vl_ + gs);
            }
            CP_COMMIT();
        }

        // ---- QK^T for this 64-col s-tile ----
        float s[8][4];
#pragma unroll
        for (int j = 0; j < 8; j++)
#pragma unroll
            for (int q = 0; q < 4; q++) s[j][q] = 0.f;

#pragma unroll
        for (int kk = 0; kk < 4; kk++) {
#pragma unroll
            for (int np = 0; np < 4; np++) {
                uint32_t bh[4], bl[4];
                uint32_t koff = (uint32_t)(((np * 16 + krow) * 72 + kcol + kk * 16) * 2);
                ldsm_x4(bh, stoff + 0 + koff);
                ldsm_x4(bl, stoff + 9216 + koff);
#pragma unroll
                for (int nt = 0; nt < 2; nt++) {
                    float* d = s[np * 2 + nt];
                    mma_bf16(d, qfh[kk], bh + nt * 2);
                    mma_bf16(d, qfl[kk], bh + nt * 2);
                    mma_bf16(d, qfh[kk], bl + nt * 2);
                }
            }
        }

        // ---- transform + mask ----
#pragma unroll
        for (int j = 0; j < 8; j++) {
            const int col = sc * 64 + j * 8 + tc;
            float2 mk0 = *(const float2*)&mrow0[col];
            float2 mk1 = *(const float2*)&mrow1[col];
            s[j][0] = (s[j][0] * tauv + deltav) * scale * mk0.x;
            s[j][1] = (s[j][1] * tauv + deltav) * scale * mk0.y;
            s[j][2] = (s[j][2] * tauv + deltav) * scale * mk1.x;
            s[j][3] = (s[j][3] * tauv + deltav) * scale * mk1.y;
        }

        // ---- online softmax update ----
        float ng = m_g, nh = m_h;
#pragma unroll
        for (int j = 0; j < 8; j++) {
            ng = fmaxf(ng, fmaxf(s[j][0], s[j][1]));
            nh = fmaxf(nh, fmaxf(s[j][2], s[j][3]));
        }
        ng = fmaxf(ng, __shfl_xor_sync(0xffffffffu, ng, 1));
        ng = fmaxf(ng, __shfl_xor_sync(0xffffffffu, ng, 2));
        nh = fmaxf(nh, __shfl_xor_sync(0xffffffffu, nh, 1));
        nh = fmaxf(nh, __shfl_xor_sync(0xffffffffu, nh, 2));

        const float ag = __expf(m_g - ng);
        const float ah_ = __expf(m_h - nh);
        m_g = ng; m_h = nh;

        float sg = 0.f, sh = 0.f;
#pragma unroll
        for (int j = 0; j < 8; j++) {
            s[j][0] = __expf(s[j][0] - ng);
            s[j][1] = __expf(s[j][1] - ng);
            s[j][2] = __expf(s[j][2] - nh);
            s[j][3] = __expf(s[j][3] - nh);
            sg += s[j][0] + s[j][1];
            sh += s[j][2] + s[j][3];
        }
        l_g = l_g * ag + sg;
        l_h = l_h * ah_ + sh;
#pragma unroll
        for (int j = 0; j < 8; j++) {
            O[j][0] *= ag; O[j][1] *= ag;
            O[j][2] *= ah_; O[j][3] *= ah_;
        }

        // ---- P @ V (in-register repack of S into A fragments) ----
#pragma unroll
        for (int mkk = 0; mkk < 4; mkk++) {
            const float* p0 = s[2 * mkk];
            const float* p1 = s[2 * mkk + 1];
            uint32_t pah[4], pal[4];
            pah[0] = pk2(p0[0], p0[1]);
            pah[1] = pk2(p0[2], p0[3]);
            pah[2] = pk2(p1[0], p1[1]);
            pah[3] = pk2(p1[2], p1[3]);
            pal[0] = pk2(rlo(p0[0]), rlo(p0[1]));
            pal[1] = pk2(rlo(p0[2]), rlo(p0[3]));
            pal[2] = pk2(rlo(p1[0]), rlo(p1[1]));
            pal[3] = pk2(rlo(p1[2]), rlo(p1[3]));
#pragma unroll
            for (int vn = 0; vn < 4; vn++) {
                uint32_t vh[4], vl[4];
                uint32_t voff = (uint32_t)(((mkk * 16 + arow) * 72 + vn * 16 + acol) * 2);
                ldsm_x4_t(vh, stoff + 18432 + voff);
                ldsm_x4_t(vl, stoff + 27648 + voff);
#pragma unroll
                for (int nt = 0; nt < 2; nt++) {
                    float* d = O[vn * 2 + nt];
                    mma_bf16(d, pah, vh + nt * 2);
                    mma_bf16(d, pal, vh + nt * 2);
                    mma_bf16(d, pah, vl + nt * 2);
                }
            }
        }
    }

    // ---- finalize: divide by row sums, write out ----
    float lg = l_g;
    lg += __shfl_xor_sync(0xffffffffu, lg, 1);
    lg += __shfl_xor_sync(0xffffffffu, lg, 2);
    float lh = l_h;
    lh += __shfl_xor_sync(0xffffffffu, lh, 1);
    lh += __shfl_xor_sync(0xffffffffu, lh, 2);
    const float ig = 1.0f / lg;
    const float ih = 1.0f / lh;

    float* dst0 = g_A + ((size_t)bth * 512 + l0 + wm * 16 + g) * 64;
#pragma unroll
    for (int vn = 0; vn < 4; vn++) {
#pragma unroll
        for (int nt = 0; nt < 2; nt++) {
            const float* d = O[vn * 2 + nt];
            const int col = vn * 16 + nt * 8 + tc;
            *(float2*)(dst0 + col)          = make_float2(d[0] * ig, d[1] * ig);
            *(float2*)(dst0 + 8 * 64 + col) = make_float2(d[2] * ih, d[3] * ih);
        }
    }
}

// ---------------------------------------------------------------------------
// Head reduction
// ---------------------------------------------------------------------------
__global__ void __launch_bounds__(256) reduce_heads(
    const float* __restrict__ w_head, float* __restrict__ out)
{
    int idx = blockIdx.x * 256 + threadIdx.x;
    int bt   = idx >> 15;
    int rest = idx & 32767;
    float s = 0.f;
#pragma unroll
    for (int h = 0; h < 8; h++)
        s += w_head[h] * g_A[(((size_t)bt * 8 + h) << 15) + rest];
    out[idx] = s;
}

// ---------------------------------------------------------------------------
extern "C" void kernel_launch(void* const* d_in, const int* in_sizes, int n_in,
                              void* d_out, int out_size)
{
    const float* queries = (const float*)d_in[0];
    const float* keys    = (const float*)d_in[1];
    const float* values  = (const float*)d_in[2];
    const float* mask    = (const float*)d_in[3];
    const float* Wq      = (const float*)d_in[4];
    const float* Wk      = (const float*)d_in[5];
    const float* Wv      = (const float*)d_in[6];
    const float* w_head  = (const float*)d_in[7];
    const float* tau     = (const float*)d_in[8];
    const float* delta   = (const float*)d_in[9];
    float* out = (float*)d_out;
    (void)in_sizes; (void)n_in; (void)out_size;

    cudaFuncSetAttribute(proj_mma,
                         cudaFuncAttributeMaxDynamicSharedMemorySize, PROJ_SMEM);
    cudaFuncSetAttribute(attn_flash,
                         cudaFuncAttributeMaxDynamicSharedMemorySize, ATT_SMEM);

    // 1) projections (tensor cores, writes pre-split bf16 hi/lo)
    {
        dim3 grid(4, 128, 3);
        proj_mma<<<grid, 256, PROJ_SMEM>>>(queries, keys, values, Wq, Wk, Wv);
    }

    // 2) flash attention (tensor cores, online softmax)
    {
        dim3 grid(256, 8);
        attn_flash<<<grid, 128, ATT_SMEM>>>(mask, tau, delta);
    }

    // 3) weighted head sum
    reduce_heads<<<4096, 256>>>(w_head, out);
}

// round 6
// speedup vs baseline: 2.6387x; 1.2560x over previous
#include <cuda_runtime.h>
#include <cuda_bf16.h>
#include <stdint.h>
#include <math.h>

// Problem constants
#define BTN 32      // B*T
#define LLEN 512    // L
#define DDIM 512    // D
#define NH 8        // H
#define ED 64       // KD == VD
#define MROWS (BTN * LLEN)   // 16384

// Scratch (device globals; allocation-free rule)
// pre-split bf16 hi/lo inputs for proj: X [src(3)][m][k], W [proj(3)][k][n]
__device__ __align__(16) __nv_bfloat16 g_Xh[3 * MROWS * DDIM];
__device__ __align__(16) __nv_bfloat16 g_Xl[3 * MROWS * DDIM];
__device__ __align__(16) __nv_bfloat16 g_Wh[3 * DDIM * DDIM];
__device__ __align__(16) __nv_bfloat16 g_Wl[3 * DDIM * DDIM];
// pre-split bf16 hi/lo Q/K/V outputs [bt][l][h*64+e]
__device__ __align__(16) __nv_bfloat16 g_Qh[MROWS * DDIM];
__device__ __align__(16) __nv_bfloat16 g_Ql[MROWS * DDIM];
__device__ __align__(16) __nv_bfloat16 g_Kh[MROWS * DDIM];
__device__ __align__(16) __nv_bfloat16 g_Kl[MROWS * DDIM];
__device__ __align__(16) __nv_bfloat16 g_Vh[MROWS * DDIM];
__device__ __align__(16) __nv_bfloat16 g_Vl[MROWS * DDIM];
__device__ float g_A[BTN * NH * LLEN * ED];

// ---------------------------------------------------------------------------
// helpers
// ---------------------------------------------------------------------------
__device__ __forceinline__ uint32_t smem_u32(const void* p) {
    uint32_t a;
    asm("{ .reg .u64 t; cvta.to.shared.u64 t, %1; cvt.u32.u64 %0, t; }"
        : "=r"(a) : "l"(p));
    return a;
}

__device__ __forceinline__ void mma_bf16(float* d, const uint32_t* a, const uint32_t* b) {
    asm volatile(
        "mma.sync.aligned.m16n8k16.row.col.f32.bf16.bf16.f32 "
        "{%0,%1,%2,%3}, {%4,%5,%6,%7}, {%8,%9}, {%0,%1,%2,%3};"
        : "+f"(d[0]), "+f"(d[1]), "+f"(d[2]), "+f"(d[3])
        : "r"(a[0]), "r"(a[1]), "r"(a[2]), "r"(a[3]), "r"(b[0]), "r"(b[1]));
}

__device__ __forceinline__ void ldsm_x4(uint32_t* r, uint32_t addr) {
    asm volatile("ldmatrix.sync.aligned.m8n8.x4.shared.b16 {%0,%1,%2,%3}, [%4];"
                 : "=r"(r[0]), "=r"(r[1]), "=r"(r[2]), "=r"(r[3]) : "r"(addr));
}
__device__ __forceinline__ void ldsm_x4_t(uint32_t* r, uint32_t addr) {
    asm volatile("ldmatrix.sync.aligned.m8n8.x4.trans.shared.b16 {%0,%1,%2,%3}, [%4];"
                 : "=r"(r[0]), "=r"(r[1]), "=r"(r[2]), "=r"(r[3]) : "r"(addr));
}

#define CP16(dst, src) \
    asm volatile("cp.async.cg.shared.global [%0], [%1], 16;" :: "r"(dst), "l"(src))
#define CP_COMMIT() asm volatile("cp.async.commit_group;" ::: "memory")
#define CP_WAIT0()  asm volatile("cp.async.wait_group 0;" ::: "memory")
#define CP_WAIT2()  asm volatile("cp.async.wait_group 2;" ::: "memory")

__device__ __forceinline__ void split_bf16(float x, uint16_t& h, uint16_t& l) {
    __nv_bfloat16 hb = __float2bfloat16(x);
    float hf = __bfloat162float(hb);
    __nv_bfloat16 lb = __float2bfloat16(x - hf);
    h = __bfloat16_as_ushort(hb);
    l = __bfloat16_as_ushort(lb);
}

__device__ __forceinline__ void pack8(const float* xs, uint4& hi, uint4& lo) {
    uint16_t hs[8], ls[8];
#pragma unroll
    for (int j = 0; j < 8; j++) split_bf16(xs[j], hs[j], ls[j]);
    hi.x = (uint32_t)hs[0] | ((uint32_t)hs[1] << 16);
    hi.y = (uint32_t)hs[2] | ((uint32_t)hs[3] << 16);
    hi.z = (uint32_t)hs[4] | ((uint32_t)hs[5] << 16);
    hi.w = (uint32_t)hs[6] | ((uint32_t)hs[7] << 16);
    lo.x = (uint32_t)ls[0] | ((uint32_t)ls[1] << 16);
    lo.y = (uint32_t)ls[2] | ((uint32_t)ls[3] << 16);
    lo.z = (uint32_t)ls[4] | ((uint32_t)ls[5] << 16);
    lo.w = (uint32_t)ls[6] | ((uint32_t)ls[7] << 16);
}

__device__ __forceinline__ uint32_t pk2(float a, float b) {
    uint32_t r;
    asm("cvt.rn.bf16x2.f32 %0, %1, %2;" : "=r"(r) : "f"(b), "f"(a));
    return r;
}
__device__ __forceinline__ float rlo(float x) {
    return x - __bfloat162float(__float2bfloat16(x));
}

// ---------------------------------------------------------------------------
// prep_x: X fp32 [m][k] -> bf16 hi/lo, per source (blockIdx.z)
// ---------------------------------------------------------------------------
__global__ void __launch_bounds__(256) prep_x(
    const float* __restrict__ q, const float* __restrict__ k, const float* __restrict__ v)
{
    const float* src = (blockIdx.z == 0) ? q : (blockIdx.z == 1) ? k : v;
    size_t base = (size_t)blockIdx.z * (MROWS * DDIM);
    size_t i = (size_t)blockIdx.x * 256 + threadIdx.x;
    const float4* s4 = (const float4*)src + i * 2;
    float4 a = s4[0], b = s4[1];
    float xs[8] = {a.x, a.y, a.z, a.w, b.x, b.y, b.z, b.w};
    uint4 hi, lo;
    pack8(xs, hi, lo);
    *(uint4*)&g_Xh[base + i * 8] = hi;
    *(uint4*)&g_Xl[base + i * 8] = lo;
}

// ---------------------------------------------------------------------------
// prep_w: W fp32 [k][n] -> bf16 hi/lo (same layout)
// ---------------------------------------------------------------------------
__global__ void __launch_bounds__(256) prep_w(
    const float* __restrict__ Wq, const float* __restrict__ Wk, const float* __restrict__ Wv)
{
    const float* src = (blockIdx.z == 0) ? Wq : (blockIdx.z == 1) ? Wk : Wv;
    size_t base = (size_t)blockIdx.z * (DDIM * DDIM);
    size_t i = (size_t)blockIdx.x * 256 + threadIdx.x;
    const float4* s4 = (const float4*)src + i * 2;
    float4 a = s4[0], b = s4[1];
    float xs[8] = {a.x, a.y, a.z, a.w, b.x, b.y, b.z, b.w};
    uint4 hi, lo;
    pack8(xs, hi, lo);
    *(uint4*)&g_Wh[base + i * 8] = hi;
    *(uint4*)&g_Wl[base + i * 8] = lo;
}

// ---------------------------------------------------------------------------
// proj_pipe: 4-stage cp.async bf16 GEMM, CTA 128x128, BK=16, 2 CTAs/SM.
// stage layout (bytes): AH 0 (128 x 24h), AL 6144, BH 12288 (16 x 136h), BL 16640
// ---------------------------------------------------------------------------
#define ST_AH 0
#define ST_AL 6144
#define ST_BH 12288
#define ST_BL 16640
#define ST_SZ 20992
#define NSTG 4
#define PROJ_SMEM (NSTG * ST_SZ)

__global__ void __launch_bounds__(256, 2) proj_pipe()
{
    extern __shared__ char smc[];
    const uint32_t sb = smem_u32(smc);

    const int tid  = threadIdx.x;
    const int wid  = tid >> 5;
    const int lane = tid & 31;
    const int wm   = wid & 3;       // 4 m-warps (32 rows)
    const int wn   = wid >> 2;      // 2 n-warps (64 cols)

    const int p  = blockIdx.z;
    const int m0 = blockIdx.y * 128;
    const int n0 = blockIdx.x * 128;

    const __nv_bfloat16* Xh_ = g_Xh + (size_t)p * (MROWS * DDIM);
    const __nv_bfloat16* Xl_ = g_Xl + (size_t)p * (MROWS * DDIM);
    const __nv_bfloat16* Wh_ = g_Wh + (size_t)p * (DDIM * DDIM);
    const __nv_bfloat16* Wl_ = g_Wl + (size_t)p * (DDIM * DDIM);
    __nv_bfloat16* Ch = (p == 0) ? g_Qh : (p == 1) ? g_Kh : g_Vh;
    __nv_bfloat16* Cl = (p == 0) ? g_Ql : (p == 1) ? g_Kl : g_Vl;

    // cp.async staging map
    const int ar = tid >> 1, ac = tid & 1;      // A: 128 rows x 2 chunks
    const int br = tid >> 4, bc = tid & 15;     // B: 16 rows x 16 chunks
    const size_t ga0 = (size_t)(m0 + ar) * 512 + ac * 8;
    const size_t gb0 = (size_t)br * 512 + n0 + bc * 8;
    const uint32_t da = ar * 48 + ac * 16;
    const uint32_t db = br * 272 + bc * 16;

    // ldsm lane offsets
    const uint32_t a_lane = (uint32_t)(((wm * 32 + (lane & 15)) * 24 + (lane >> 4) * 8) * 2);
    const uint32_t b_lane = (uint32_t)(((lane & 15) * 136 + wn * 64 + (lane >> 4) * 8) * 2);

    float acc[2][8][4];
#pragma unroll
    for (int i = 0; i < 2; i++)
#pragma unroll
        for (int j = 0; j < 8; j++)
#pragma unroll
            for (int q = 0; q < 4; q++) acc[i][j][q] = 0.f;

    // prologue: issue stages 0..2
#pragma unroll
    for (int s = 0; s < 3; s++) {
        const uint32_t st = sb + s * ST_SZ;
        const size_t ka = (size_t)s * 16;
        CP16(st + ST_AH + da, Xh_ + ga0 + ka);
        CP16(st + ST_AL + da, Xl_ + ga0 + ka);
        CP16(st + ST_BH + db, Wh_ + gb0 + ka * 512);
        CP16(st + ST_BL + db, Wl_ + gb0 + ka * 512);
        CP_COMMIT();
    }

    for (int c = 0; c < 32; c++) {
        CP_WAIT2();
        __syncthreads();

        // refill buffer (c+3)%4 == (c-1)%4 (consumed last iter; safe post-sync)
        if (c + 3 < 32) {
            const uint32_t st = sb + ((c + 3) & 3) * ST_SZ;
            const size_t ka = (size_t)(c + 3) * 16;
            CP16(st + ST_AH + da, Xh_ + ga0 + ka);
            CP16(st + ST_AL + da, Xl_ + ga0 + ka);
            CP16(st + ST_BH + db, Wh_ + gb0 + ka * 512);
            CP16(st + ST_BL + db, Wl_ + gb0 + ka * 512);
        }
        CP_COMMIT();   // always commit (empty groups keep the count aligned)

        // compute stage c
        const uint32_t stc = sb + (c & 3) * ST_SZ;
        uint32_t ah[2][4], al[2][4];
#pragma unroll
        for (int mt = 0; mt < 2; mt++) {
            const uint32_t ao = stc + a_lane + mt * 768;   // 16*24*2
            ldsm_x4(ah[mt], ao + ST_AH);
            ldsm_x4(al[mt], ao + ST_AL);
        }
#pragma unroll
        for (int np = 0; np < 4; np++) {
            uint32_t bh[4], bl[4];
            const uint32_t bo = stc + b_lane + np * 32;    // 16 halves
            ldsm_x4_t(bh, bo + ST_BH);
            ldsm_x4_t(bl, bo + ST_BL);
#pragma unroll
            for (int mt = 0; mt < 2; mt++) {
#pragma unroll
                for (int nt = 0; nt < 2; nt++) {
                    float* d = acc[mt][np * 2 + nt];
                    mma_bf16(d, ah[mt], bh + nt * 2);
                    mma_bf16(d, al[mt], bh + nt * 2);
                    mma_bf16(d, ah[mt], bl + nt * 2);
                }
            }
        }
    }

    // epilogue: split fp32 accumulators into bf16 hi/lo global
    const int g = lane >> 2;
    const int t = lane & 3;
#pragma unroll
    for (int mt = 0; mt < 2; mt++) {
#pragma unroll
        for (int np = 0; np < 4; np++) {
#pragma unroll
            for (int nt = 0; nt < 2; nt++) {
                const float* d = acc[mt][np * 2 + nt];
                int row = m0 + wm * 32 + mt * 16 + g;
                int col = n0 + wn * 64 + np * 16 + nt * 8 + t * 2;
                uint16_t h0, l0, h1, l1;
                split_bf16(d[0], h0, l0);
                split_bf16(d[1], h1, l1);
                *(uint32_t*)(Ch + (size_t)row * 512 + col) = (uint32_t)h0 | ((uint32_t)h1 << 16);
                *(uint32_t*)(Cl + (size_t)row * 512 + col) = (uint32_t)l0 | ((uint32_t)l1 << 16);
                split_bf16(d[2], h0, l0);
                split_bf16(d[3], h1, l1);
                *(uint32_t*)(Ch + (size_t)(row + 8) * 512 + col) = (uint32_t)h0 | ((uint32_t)h1 << 16);
                *(uint32_t*)(Cl + (size_t)(row + 8) * 512 + col) = (uint32_t)l0 | ((uint32_t)l1 << 16);
            }
        }
    }
}

// ---------------------------------------------------------------------------
// Flash attention (R5, passing): 1 CTA (128 thr) per (bth, 64-row l-chunk)
// ---------------------------------------------------------------------------
#define AQH 0
#define AQL 9216
#define AST 18432
#define STG 36864
#define ATT_SMEM 92160

__global__ void __launch_bounds__(128, 2) attn_flash(
    const float* __restrict__ mask,
    const float* __restrict__ tau,
    const float* __restrict__ delta)
{
    extern __shared__ char smc[];
    const uint32_t sb = smem_u32(smc);

    const int tid  = threadIdx.x;
    const int wid  = tid >> 5;
    const int lane = tid & 31;
    const int wm   = wid;

    const int bth = blockIdx.x;
    const int bt  = bth >> 3;
    const int h   = bth & 7;
    const int l0  = blockIdx.y * 64;

    const float tauv   = tau[0];
    const float deltav = delta[0];
    const float scale  = 0.125f;

    const size_t hb = (size_t)bt * 512 * 512 + h * 64;
    const __nv_bfloat16* Kh_ = g_Kh + hb;
    const __nv_bfloat16* Kl_ = g_Kl + hb;
    const __nv_bfloat16* Vh_ = g_Vh + hb;
    const __nv_bfloat16* Vl_ = g_Vl + hb;

    const int arow = lane & 15;
    const int acol = (lane >> 4) * 8;
    const int krow = (lane & 7) | ((lane & 16) >> 1);
    const int kcol = lane & 8;
    const int g    = lane >> 2;
    const int tc   = (lane & 3) * 2;

    {
#pragma unroll
        for (int i = 0; i < 4; i++) {
            int q = tid + i * 128;
            int row = q >> 3, c16 = q & 7;
            size_t gs = (size_t)row * 512 + c16 * 8;
            uint32_t dr = sb + AST + row * 144 + c16 * 16;
            CP16(dr +     0, Kh_ + gs);
            CP16(dr +  9216, Kl_ + gs);
            CP16(dr + 18432, Vh_ + gs);
            CP16(dr + 27648, Vl_ + gs);
        }
        CP_COMMIT();
    }

    {
        const __nv_bfloat16* Qh_ = g_Qh + hb + (size_t)l0 * 512;
        const __nv_bfloat16* Ql_ = g_Ql + hb + (size_t)l0 * 512;
#pragma unroll
        for (int i = 0; i < 8; i++) {
            int arr = i >> 2;
            int q = tid + (i & 3) * 128;
            int row = q >> 3, c16 = q & 7;
            size_t gs = (size_t)row * 512 + c16 * 8;
            const __nv_bfloat16* src = arr ? Ql_ : Qh_;
            *(uint4*)(smc + (arr ? AQL : AQH) + row * 144 + c16 * 16) =
                *(const uint4*)(src + gs);
        }
    }
    __syncthreads();

    uint32_t qfh[4][4], qfl[4][4];
#pragma unroll
    for (int kk = 0; kk < 4; kk++) {
        uint32_t qoff = (uint32_t)(((wm * 16 + arow) * 72 + acol + kk * 16) * 2);
        ldsm_x4(qfh[kk], sb + AQH + qoff);
        ldsm_x4(qfl[kk], sb + AQL + qoff);
    }

    float O[8][4];
#pragma unroll
    for (int j = 0; j < 8; j++)
#pragma unroll
        for (int q = 0; q < 4; q++) O[j][q] = 0.f;
    float m_g = -1e30f, m_h = -1e30f, l_g = 0.f, l_h = 0.f;

    const float* mrow0 = mask + (size_t)(l0 + wm * 16 + g) * 512;
    const float* mrow1 = mrow0 + 8 * 512;

    for (int sc = 0; sc < 8; sc++) {
        CP_WAIT0();
        __syncthreads();
        const uint32_t stoff = sb + AST + (sc & 1) * STG;

        if (sc < 7) {
            const int s_row0 = (sc + 1) * 64;
            const uint32_t nst = sb + AST + ((sc + 1) & 1) * STG;
#pragma unroll
            for (int i = 0; i < 4; i++) {
                int q = tid + i * 128;
                int row = q >> 3, c16 = q & 7;
                size_t gs = (size_t)(s_row0 + row) * 512 + c16 * 8;
                uint32_t dr = nst + row * 144 + c16 * 16;
                CP16(dr +     0, Kh_ + gs);
                CP16(dr +  9216, Kl_ + gs);
                CP16(dr + 18432, Vh_ + gs);
                CP16(dr + 27648, Vl_ + gs);
            }
            CP_COMMIT();
        }

        float s[8][4];
#pragma unroll
        for (int j = 0; j < 8; j++)
#pragma unroll
            for (int q = 0; q < 4; q++) s[j][q] = 0.f;

#pragma unroll
        for (int kk = 0; kk < 4; kk++) {
#pragma unroll
            for (int np = 0; np < 4; np++) {
                uint32_t bh[4], bl[4];
                uint32_t koff = (uint32_t)(((np * 16 + krow) * 72 + kcol + kk * 16) * 2);
                ldsm_x4(bh, stoff + 0 + koff);
                ldsm_x4(bl, stoff + 9216 + koff);
#pragma unroll
                for (int nt = 0; nt < 2; nt++) {
                    float* d = s[np * 2 + nt];
                    mma_bf16(d, qfh[kk], bh + nt * 2);
                    mma_bf16(d, qfl[kk], bh + nt * 2);
                    mma_bf16(d, qfh[kk], bl + nt * 2);
                }
            }
        }

#pragma unroll
        for (int j = 0; j < 8; j++) {
            const int col = sc * 64 + j * 8 + tc;
            float2 mk0 = *(const float2*)&mrow0[col];
            float2 mk1 = *(const float2*)&mrow1[col];
            s[j][0] = (s[j][0] * tauv + deltav) * scale * mk0.x;
            s[j][1] = (s[j][1] * tauv + deltav) * scale * mk0.y;
            s[j][2] = (s[j][2] * tauv + deltav) * scale * mk1.x;
            s[j][3] = (s[j][3] * tauv + deltav) * scale * mk1.y;
        }

        float ng = m_g, nh = m_h;
#pragma unroll
        for (int j = 0; j < 8; j++) {
            ng = fmaxf(ng, fmaxf(s[j][0], s[j][1]));
            nh = fmaxf(nh, fmaxf(s[j][2], s[j][3]));
        }
        ng = fmaxf(ng, __shfl_xor_sync(0xffffffffu, ng, 1));
        ng = fmaxf(ng, __shfl_xor_sync(0xffffffffu, ng, 2));
        nh = fmaxf(nh, __shfl_xor_sync(0xffffffffu, nh, 1));
        nh = fmaxf(nh, __shfl_xor_sync(0xffffffffu, nh, 2));

        const float ag = __expf(m_g - ng);
        const float ah_ = __expf(m_h - nh);
        m_g = ng; m_h = nh;

        float sg = 0.f, sh = 0.f;
#pragma unroll
        for (int j = 0; j < 8; j++) {
            s[j][0] = __expf(s[j][0] - ng);
            s[j][1] = __expf(s[j][1] - ng);
            s[j][2] = __expf(s[j][2] - nh);
            s[j][3] = __expf(s[j][3] - nh);
            sg += s[j][0] + s[j][1];
            sh += s[j][2] + s[j][3];
        }
        l_g = l_g * ag + sg;
        l_h = l_h * ah_ + sh;
#pragma unroll
        for (int j = 0; j < 8; j++) {
            O[j][0] *= ag; O[j][1] *= ag;
            O[j][2] *= ah_; O[j][3] *= ah_;
        }

#pragma unroll
        for (int mkk = 0; mkk < 4; mkk++) {
            const float* p0 = s[2 * mkk];
            const float* p1 = s[2 * mkk + 1];
            uint32_t pah[4], pal[4];
            pah[0] = pk2(p0[0], p0[1]);
            pah[1] = pk2(p0[2], p0[3]);
            pah[2] = pk2(p1[0], p1[1]);
            pah[3] = pk2(p1[2], p1[3]);
            pal[0] = pk2(rlo(p0[0]), rlo(p0[1]));
            pal[1] = pk2(rlo(p0[2]), rlo(p0[3]));
            pal[2] = pk2(rlo(p1[0]), rlo(p1[1]));
            pal[3] = pk2(rlo(p1[2]), rlo(p1[3]));
#pragma unroll
            for (int vn = 0; vn < 4; vn++) {
                uint32_t vh[4], vl[4];
                uint32_t voff = (uint32_t)(((mkk * 16 + arow) * 72 + vn * 16 + acol) * 2);
                ldsm_x4_t(vh, stoff + 18432 + voff);
                ldsm_x4_t(vl, stoff + 27648 + voff);
#pragma unroll
                for (int nt = 0; nt < 2; nt++) {
                    float* d = O[vn * 2 + nt];
                    mma_bf16(d, pah, vh + nt * 2);
                    mma_bf16(d, pal, vh + nt * 2);
                    mma_bf16(d, pah, vl + nt * 2);
                }
            }
        }
    }

    float lg = l_g;
    lg += __shfl_xor_sync(0xffffffffu, lg, 1);
    lg += __shfl_xor_sync(0xffffffffu, lg, 2);
    float lh = l_h;
    lh += __shfl_xor_sync(0xffffffffu, lh, 1);
    lh += __shfl_xor_sync(0xffffffffu, lh, 2);
    const float ig = 1.0f / lg;
    const float ih = 1.0f / lh;

    float* dst0 = g_A + ((size_t)bth * 512 + l0 + wm * 16 + g) * 64;
#pragma unroll
    for (int vn = 0; vn < 4; vn++) {
#pragma unroll
        for (int nt = 0; nt < 2; nt++) {
            const float* d = O[vn * 2 + nt];
            const int col = vn * 16 + nt * 8 + tc;
            *(float2*)(dst0 + col)          = make_float2(d[0] * ig, d[1] * ig);
            *(float2*)(dst0 + 8 * 64 + col) = make_float2(d[2] * ih, d[3] * ih);
        }
    }
}

// ---------------------------------------------------------------------------
// Head reduction
// ---------------------------------------------------------------------------
__global__ void __launch_bounds__(256) reduce_heads(
    const float* __restrict__ w_head, float* __restrict__ out)
{
    int idx = blockIdx.x * 256 + threadIdx.x;
    int bt   = idx >> 15;
    int rest = idx & 32767;
    float s = 0.f;
#pragma unroll
    for (int h = 0; h < 8; h++)
        s += w_head[h] * g_A[(((size_t)bt * 8 + h) << 15) + rest];
    out[idx] = s;
}

// ---------------------------------------------------------------------------
extern "C" void kernel_launch(void* const* d_in, const int* in_sizes, int n_in,
                              void* d_out, int out_size)
{
    const float* queries = (const float*)d_in[0];
    const float* keys    = (const float*)d_in[1];
    const float* values  = (const float*)d_in[2];
    const float* mask    = (const float*)d_in[3];
    const float* Wq      = (const float*)d_in[4];
    const float* Wk      = (const float*)d_in[5];
    const float* Wv      = (const float*)d_in[6];
    const float* w_head  = (const float*)d_in[7];
    const float* tau     = (const float*)d_in[8];
    const float* delta   = (const float*)d_in[9];
    float* out = (float*)d_out;
    (void)in_sizes; (void)n_in; (void)out_size;

    cudaFuncSetAttribute(proj_pipe,
                         cudaFuncAttributeMaxDynamicSharedMemorySize, PROJ_SMEM);
    cudaFuncSetAttribute(attn_flash,
                         cudaFuncAttributeMaxDynamicSharedMemorySize, ATT_SMEM);

    // 0) fp32 -> bf16 hi/lo conversion (streaming)
    prep_x<<<dim3(4096, 1, 3), 256>>>(queries, keys, values);
    prep_w<<<dim3(128, 1, 3), 256>>>(Wq, Wk, Wv);

    // 1) projections: pipelined tensor-core GEMM
    proj_pipe<<<dim3(4, 128, 3), 256, PROJ_SMEM>>>();

    // 2) flash attention
    attn_flash<<<dim3(256, 8), 128, ATT_SMEM>>>(mask, tau, delta);

    // 3) weighted head sum
    reduce_heads<<<4096, 256>>>(w_head, out);
}